// round 7
// baseline (speedup 1.0000x reference)
#include <cuda_runtime.h>
#include <math.h>
#include <stdint.h>

#define BATCH 2
#define SEQ   2048
#define DIM   1024
#define NHEAD 16
#define HDIM  64
#define NTOK  (BATCH*SEQ)   // 4096

// ---------------------------------------------------------------------------
// Scratch
// ---------------------------------------------------------------------------
__device__ float g_zn  [NTOK*DIM];
__device__ float g_cn  [NTOK*DIM];
__device__ float g_hf  [NTOK*2*DIM];
__device__ float g_dzl [NTOK*DIM];
__device__ float g_gh  [NTOK*DIM];
__device__ float g_dz  [NTOK*DIM];
__device__ float g_QK  [NTOK*2*DIM];   // packed: cols [0,1024)=Q, [1024,2048)=K
__device__ float g_V   [NTOK*DIM];
__device__ float g_attn[NTOK*DIM];
__device__ float g_z1  [NTOK*DIM];
__device__ float g_hcu [NTOK*2*DIM];
__device__ float g_z1n [NTOK*DIM];
__device__ float g_h4  [NTOK*4*DIM];

// ---------------------------------------------------------------------------
// helpers
// ---------------------------------------------------------------------------
__device__ __forceinline__ uint32_t f2tf32(float f)
{
    uint32_t r;
    asm("cvt.rna.tf32.f32 %0, %1;" : "=r"(r) : "f"(f));
    return r;
}

__device__ __forceinline__ void mma_tf32(float* c, const uint32_t* a, const uint32_t* b)
{
    asm volatile("mma.sync.aligned.m16n8k8.row.col.f32.tf32.tf32.f32 "
                 "{%0,%1,%2,%3}, {%4,%5,%6,%7}, {%8,%9}, {%0,%1,%2,%3};"
                 : "+f"(c[0]), "+f"(c[1]), "+f"(c[2]), "+f"(c[3])
                 : "r"(a[0]), "r"(a[1]), "r"(a[2]), "r"(a[3]),
                   "r"(b[0]), "r"(b[1]));
}

__device__ __forceinline__ void cpasync16(uint32_t saddr, const void* g)
{
    asm volatile("cp.async.cg.shared.global [%0], [%1], 16;\n" :: "r"(saddr), "l"(g));
}

// ---------------------------------------------------------------------------
// Fused RMSNorm pair
// ---------------------------------------------------------------------------
__global__ void rms2_kernel(const float* __restrict__ x0, const float* __restrict__ w0,
                            float* __restrict__ o0,
                            const float* __restrict__ x1, const float* __restrict__ w1,
                            float* __restrict__ o1)
{
    int rid = blockIdx.x;
    const float* x; const float* w; float* o; int row;
    if (rid < NTOK) { x = x0; w = w0; o = o0; row = rid; }
    else            { x = x1; w = w1; o = o1; row = rid - NTOK; }

    int t = threadIdx.x;
    const float4* xr = (const float4*)(x + (size_t)row * DIM);
    float4 v = xr[t];
    float ss = v.x*v.x + v.y*v.y + v.z*v.z + v.w*v.w;

    __shared__ float red[256];
    red[t] = ss;
    __syncthreads();
    for (int s = 128; s > 0; s >>= 1) {
        if (t < s) red[t] += red[t + s];
        __syncthreads();
    }
    float inv = rsqrtf(red[0] * (1.0f / DIM) + 1e-6f);
    float4 wv = ((const float4*)w)[t];
    float4 ov;
    ov.x = v.x * inv * wv.x;
    ov.y = v.y * inv * wv.y;
    ov.z = v.z * inv * wv.z;
    ov.w = v.w * inv * wv.w;
    ((float4*)(o + (size_t)row * DIM))[t] = ov;
}

__global__ void rms_kernel(const float* __restrict__ x, const float* __restrict__ w,
                           float* __restrict__ o)
{
    int row = blockIdx.x;
    int t   = threadIdx.x;
    const float4* xr = (const float4*)(x + (size_t)row * DIM);
    float4 v = xr[t];
    float ss = v.x*v.x + v.y*v.y + v.z*v.z + v.w*v.w;

    __shared__ float red[256];
    red[t] = ss;
    __syncthreads();
    for (int s = 128; s > 0; s >>= 1) {
        if (t < s) red[t] += red[t + s];
        __syncthreads();
    }
    float inv = rsqrtf(red[0] * (1.0f / DIM) + 1e-6f);
    float4 wv = ((const float4*)w)[t];
    float4 ov;
    ov.x = v.x * inv * wv.x;
    ov.y = v.y * inv * wv.y;
    ov.z = v.z * inv * wv.z;
    ov.w = v.w * inv * wv.w;
    ((float4*)(o + (size_t)row * DIM))[t] = ov;
}

// ---------------------------------------------------------------------------
// TF32 tensor-core GEMM, templated block-M:
//   C = EPI( ACT( gatherA @ W^T + bias ) )
// A: up to 4 K-segments of width 1024 (concat fusion).
// W: row-segmented at 'wsplit' between W0 / W1 (merged QK projection).
// Tile BMTx128xBK32, 8 warps, warp tile (BMT/4)x64, cp.async double-buffered.
// EPI: 0 none | 1 +res1 | 2 dt*(res1+v) | 3 v+res1+res2
// ACT: 0 none | 1 silu | 2 tanh
// ---------------------------------------------------------------------------
#define BN 128
#define BK 32
#define KST 36

template<int BMT, int ACT, int EPI, bool HAS_BIAS>
__global__ __launch_bounds__(256)
void gemm_tc_kernel(const float* __restrict__ p0, const float* __restrict__ p1,
                    const float* __restrict__ p2, const float* __restrict__ p3,
                    int s0, int s1, int s2, int s3,
                    const float* __restrict__ W0, const float* __restrict__ W1,
                    int wsplit,
                    const float* __restrict__ bias,
                    const float* __restrict__ res1, const float* __restrict__ res2,
                    const float* __restrict__ dtp,
                    float* __restrict__ C, int M, int N, int K)
{
    constexpr int ITS_A = BMT / 32;      // float4 loads per thread for A
    constexpr int MI    = BMT / 64;      // 16-row mma slices per warp
    constexpr int SA    = BMT * KST;     // floats per A stage
    constexpr int SW    = BN * KST;      // floats per W stage

    extern __shared__ float dsm[];
    const uint32_t smem0 = (uint32_t)__cvta_generic_to_shared(dsm);

    const int bm = blockIdx.y * BMT;
    const int bn = blockIdx.x * BN;
    const int tid  = threadIdx.x;
    const int warp = tid >> 5;
    const int lane = tid & 31;
    const int gid  = lane >> 2;
    const int tig  = lane & 3;
    const int wm   = warp >> 1;
    const int wn   = warp & 1;

    const int rbase = tid >> 3;          // 0..31
    const int c4    = (tid & 7) * 4;     // float col within BK

    const float* Wb = (bn < wsplit) ? (W0 + (size_t)bn * K)
                                    : (W1 + (size_t)(bn - wsplit) * K);

    float acc[MI][8][4];
    #pragma unroll
    for (int mi = 0; mi < MI; mi++)
        #pragma unroll
        for (int ni = 0; ni < 8; ni++)
            #pragma unroll
            for (int r = 0; r < 4; r++) acc[mi][ni][r] = 0.0f;

    const int KT = K / BK;

    #define PREFETCH(KT_IDX, BUF)                                                   \
    {                                                                               \
        const int gk  = (KT_IDX) * BK;                                              \
        const int seg = gk >> 10;                                                   \
        const float* sp = (seg == 0) ? p0 : (seg == 1) ? p1 : (seg == 2) ? p2 : p3; \
        const int    st = (seg == 0) ? s0 : (seg == 1) ? s1 : (seg == 2) ? s2 : s3; \
        const int    ko = (gk & 1023) + c4;                                         \
        _Pragma("unroll")                                                           \
        for (int it = 0; it < ITS_A; it++) {                                        \
            int r = rbase + it * 32;                                                \
            uint32_t da = smem0 + ((BUF) * SA + r * KST + c4) * 4;                  \
            cpasync16(da, sp + (size_t)(bm + r) * st + ko);                         \
        }                                                                           \
        _Pragma("unroll")                                                           \
        for (int it = 0; it < 4; it++) {                                            \
            int r = rbase + it * 32;                                                \
            uint32_t dw = smem0 + (2 * SA + (BUF) * SW + r * KST + c4) * 4;         \
            cpasync16(dw, Wb + (size_t)r * K + gk + c4);                            \
        }                                                                           \
        asm volatile("cp.async.commit_group;\n");                                   \
    }

    PREFETCH(0, 0);

    int buf = 0;
    for (int kt = 0; kt < KT; kt++) {
        if (kt + 1 < KT) {
            PREFETCH(kt + 1, buf ^ 1);
            asm volatile("cp.async.wait_group 1;\n");
        } else {
            asm volatile("cp.async.wait_group 0;\n");
        }
        __syncthreads();

        const float* sA = dsm + buf * SA;
        const float* sW = dsm + 2 * SA + buf * SW;

        #pragma unroll
        for (int k0 = 0; k0 < BK; k0 += 8) {
            uint32_t afr[MI][4], bfr[8][2];
            #pragma unroll
            for (int mi = 0; mi < MI; mi++) {
                int rr = wm * (BMT / 4) + mi * 16 + gid;
                afr[mi][0] = f2tf32(sA[(rr    ) * KST + k0 + tig    ]);
                afr[mi][1] = f2tf32(sA[(rr + 8) * KST + k0 + tig    ]);
                afr[mi][2] = f2tf32(sA[(rr    ) * KST + k0 + tig + 4]);
                afr[mi][3] = f2tf32(sA[(rr + 8) * KST + k0 + tig + 4]);
            }
            #pragma unroll
            for (int ni = 0; ni < 8; ni++) {
                int cc = wn * 64 + ni * 8 + gid;
                bfr[ni][0] = f2tf32(sW[cc * KST + k0 + tig    ]);
                bfr[ni][1] = f2tf32(sW[cc * KST + k0 + tig + 4]);
            }
            #pragma unroll
            for (int mi = 0; mi < MI; mi++)
                #pragma unroll
                for (int ni = 0; ni < 8; ni++)
                    mma_tf32(acc[mi][ni], afr[mi], bfr[ni]);
        }
        __syncthreads();
        buf ^= 1;
    }
    #undef PREFETCH

    const float dtv = (EPI == 2) ? dtp[0] : 0.0f;

    #pragma unroll
    for (int mi = 0; mi < MI; mi++) {
        int row = bm + wm * (BMT / 4) + mi * 16 + gid;
        #pragma unroll
        for (int ni = 0; ni < 8; ni++) {
            int col = bn + wn * 64 + ni * 8 + 2 * tig;
            float b0 = 0.f, b1 = 0.f;
            if (HAS_BIAS) { b0 = bias[col]; b1 = bias[col + 1]; }
            #pragma unroll
            for (int half = 0; half < 2; half++) {
                int r = row + half * 8;
                float v0 = acc[mi][ni][half * 2 + 0] + b0;
                float v1 = acc[mi][ni][half * 2 + 1] + b1;
                if (ACT == 1) { v0 = v0 / (1.0f + __expf(-v0)); v1 = v1 / (1.0f + __expf(-v1)); }
                else if (ACT == 2) { v0 = tanhf(v0); v1 = tanhf(v1); }
                if (EPI == 1) {
                    const float2 rv = *(const float2*)(res1 + (size_t)r * N + col);
                    v0 += rv.x; v1 += rv.y;
                } else if (EPI == 2) {
                    const float2 rv = *(const float2*)(res1 + (size_t)r * N + col);
                    v0 = dtv * (rv.x + v0); v1 = dtv * (rv.y + v1);
                } else if (EPI == 3) {
                    const float2 ra = *(const float2*)(res1 + (size_t)r * N + col);
                    const float2 rb = *(const float2*)(res2 + (size_t)r * N + col);
                    v0 += ra.x + rb.x; v1 += ra.y + rb.y;
                }
                *(float2*)(C + (size_t)r * N + col) = make_float2(v0, v1);
            }
        }
    }
}

// ---------------------------------------------------------------------------
// Sigmoid attention on tensor cores (tf32 mma.sync flash-style).
// Q/K read from packed [NTOK, 2048] buffer (stride qstr); V/O stride DIM.
// ---------------------------------------------------------------------------
#define AQ  128
#define AKV 32

__global__ __launch_bounds__(256)
void attn_tc_kernel(const float* __restrict__ Qp, const float* __restrict__ Kp,
                    int qstr,
                    const float* __restrict__ V, const float* __restrict__ temp,
                    float* __restrict__ O)
{
    __shared__ float Ks[AKV][68];
    __shared__ float Vs[AKV][72];
    __shared__ float Ps[AQ][68];

    const int b = blockIdx.z, h = blockIdx.y;
    const int q0 = blockIdx.x * AQ;
    const int tid = threadIdx.x;
    const int warp = tid >> 5, lane = tid & 31;
    const int gid = lane >> 2, tig = lane & 3;

    const float scale = 0.125f * temp[0];
    const size_t baseq  = ((size_t)(b * SEQ + q0)) * qstr + h * HDIM;
    const size_t basek  = ((size_t)(b * SEQ)) * qstr + h * HDIM;
    const size_t basev  = ((size_t)(b * SEQ)) * DIM + h * HDIM;
    const size_t baseo  = ((size_t)(b * SEQ + q0)) * DIM + h * HDIM;

    const int r0 = warp * 16 + gid;

    uint32_t qfr[8][4];
    {
        const float* Qr0 = Qp + baseq + (size_t)r0 * qstr;
        const float* Qr1 = Qr0 + (size_t)8 * qstr;
        #pragma unroll
        for (int kc = 0; kc < 8; kc++) {
            qfr[kc][0] = f2tf32(Qr0[kc * 8 + tig    ]);
            qfr[kc][1] = f2tf32(Qr1[kc * 8 + tig    ]);
            qfr[kc][2] = f2tf32(Qr0[kc * 8 + tig + 4]);
            qfr[kc][3] = f2tf32(Qr1[kc * 8 + tig + 4]);
        }
    }

    float acc_o[8][4];
    #pragma unroll
    for (int nb = 0; nb < 8; nb++)
        #pragma unroll
        for (int r = 0; r < 4; r++) acc_o[nb][r] = 0.0f;
    float rs0 = 0.0f, rs1 = 0.0f;

    for (int m0 = 0; m0 < SEQ; m0 += AKV) {
        __syncthreads();
        #pragma unroll
        for (int it = 0; it < 2; it++) {
            int f = tid + it * 256;
            int r = f >> 4, c4 = (f & 15) * 4;
            float4 kv = *(const float4*)(Kp + basek + (size_t)(m0 + r) * qstr + c4);
            Ks[r][c4] = kv.x; Ks[r][c4 + 1] = kv.y; Ks[r][c4 + 2] = kv.z; Ks[r][c4 + 3] = kv.w;
            float4 vv = *(const float4*)(V + basev + (size_t)(m0 + r) * DIM + c4);
            Vs[r][c4] = vv.x; Vs[r][c4 + 1] = vv.y; Vs[r][c4 + 2] = vv.z; Vs[r][c4 + 3] = vv.w;
        }
        __syncthreads();

        float acc_s[4][4] = {};
        #pragma unroll
        for (int kc = 0; kc < 8; kc++) {
            uint32_t bfr[4][2];
            #pragma unroll
            for (int nb = 0; nb < 4; nb++) {
                bfr[nb][0] = f2tf32(Ks[nb * 8 + gid][kc * 8 + tig    ]);
                bfr[nb][1] = f2tf32(Ks[nb * 8 + gid][kc * 8 + tig + 4]);
            }
            #pragma unroll
            for (int nb = 0; nb < 4; nb++)
                mma_tf32(acc_s[nb], qfr[kc], bfr[nb]);
        }

        #pragma unroll
        for (int nb = 0; nb < 4; nb++) {
            float s00 = 1.0f / (1.0f + __expf(-acc_s[nb][0] * scale));
            float s01 = 1.0f / (1.0f + __expf(-acc_s[nb][1] * scale));
            float s10 = 1.0f / (1.0f + __expf(-acc_s[nb][2] * scale));
            float s11 = 1.0f / (1.0f + __expf(-acc_s[nb][3] * scale));
            rs0 += s00 + s01;
            rs1 += s10 + s11;
            *(float2*)&Ps[r0    ][nb * 8 + 2 * tig] = make_float2(s00, s01);
            *(float2*)&Ps[r0 + 8][nb * 8 + 2 * tig] = make_float2(s10, s11);
        }
        __syncwarp();

        #pragma unroll
        for (int kc = 0; kc < 4; kc++) {
            uint32_t afr[4];
            afr[0] = f2tf32(Ps[r0    ][kc * 8 + tig    ]);
            afr[1] = f2tf32(Ps[r0 + 8][kc * 8 + tig    ]);
            afr[2] = f2tf32(Ps[r0    ][kc * 8 + tig + 4]);
            afr[3] = f2tf32(Ps[r0 + 8][kc * 8 + tig + 4]);
            #pragma unroll
            for (int nb = 0; nb < 8; nb++) {
                uint32_t bfr[2];
                bfr[0] = f2tf32(Vs[kc * 8 + tig    ][nb * 8 + gid]);
                bfr[1] = f2tf32(Vs[kc * 8 + tig + 4][nb * 8 + gid]);
                mma_tf32(acc_o[nb], afr, bfr);
            }
        }
        __syncwarp();
    }

    rs0 += __shfl_xor_sync(0xffffffffu, rs0, 1);
    rs0 += __shfl_xor_sync(0xffffffffu, rs0, 2);
    rs1 += __shfl_xor_sync(0xffffffffu, rs1, 1);
    rs1 += __shfl_xor_sync(0xffffffffu, rs1, 2);
    const float inv0 = 1.0f / fmaxf(rs0, 1.0f);
    const float inv1 = 1.0f / fmaxf(rs1, 1.0f);

    float* O0 = O + baseo + (size_t)r0 * DIM;
    float* O1 = O0 + 8 * DIM;
    #pragma unroll
    for (int nb = 0; nb < 8; nb++) {
        int col = nb * 8 + 2 * tig;
        *(float2*)(O0 + col) = make_float2(acc_o[nb][0] * inv0, acc_o[nb][1] * inv0);
        *(float2*)(O1 + col) = make_float2(acc_o[nb][2] * inv1, acc_o[nb][3] * inv1);
    }
}

// ---------------------------------------------------------------------------
// Host-side dispatch
// ---------------------------------------------------------------------------
struct Seg { const float* p; int s; };

template<int BMT, int ACT, int EPI, bool HAS_BIAS>
static void launch_gemm2(const Seg* seg, int nseg,
                         const float* W0, const float* W1, int wsplit,
                         const float* bias,
                         const float* res1, const float* res2, const float* dtp,
                         float* C, int M, int N, int K)
{
    constexpr int SMEM = (2 * BMT * KST + 2 * BN * KST) * 4;
    cudaFuncSetAttribute(gemm_tc_kernel<BMT, ACT, EPI, HAS_BIAS>,
                         cudaFuncAttributeMaxDynamicSharedMemorySize, SMEM);
    const float* p0 = seg[0].p;                     int s0 = seg[0].s;
    const float* p1 = (nseg > 1) ? seg[1].p : p0;   int s1 = (nseg > 1) ? seg[1].s : s0;
    const float* p2 = (nseg > 2) ? seg[2].p : p0;   int s2 = (nseg > 2) ? seg[2].s : s0;
    const float* p3 = (nseg > 3) ? seg[3].p : p0;   int s3 = (nseg > 3) ? seg[3].s : s0;
    dim3 g(N / BN, M / BMT), b(256);
    gemm_tc_kernel<BMT, ACT, EPI, HAS_BIAS><<<g, b, SMEM>>>(
        p0, p1, p2, p3, s0, s1, s2, s3, W0, W1, wsplit,
        bias, res1, res2, dtp, C, M, N, K);
}

template<int BMT, int ACT, int EPI, bool HAS_BIAS>
static void launch_gemm(const Seg* seg, int nseg, const float* W, const float* bias,
                        const float* res1, const float* res2, const float* dtp,
                        float* C, int M, int N, int K)
{
    launch_gemm2<BMT, ACT, EPI, HAS_BIAS>(seg, nseg, W, W, 1 << 30,
                                          bias, res1, res2, dtp, C, M, N, K);
}

static float* sym(const void* s)
{
    void* p = nullptr;
    cudaGetSymbolAddress(&p, s);
    return (float*)p;
}

extern "C" void kernel_launch(void* const* d_in, const int* in_sizes, int n_in,
                              void* d_out, int out_size)
{
    const float* z     = (const float*)d_in[0];
    const float* conn  = (const float*)d_in[1];
    const float* w_z   = (const float*)d_in[2];
    const float* w_c   = (const float*)d_in[3];
    const float* w_mlp = (const float*)d_in[4];
    const float* f_w1  = (const float*)d_in[5];
    const float* f_b1  = (const float*)d_in[6];
    const float* f_w2  = (const float*)d_in[7];
    const float* f_b2  = (const float*)d_in[8];
    const float* g_w1  = (const float*)d_in[9];
    const float* g_b1  = (const float*)d_in[10];
    const float* g_w2  = (const float*)d_in[11];
    const float* g_b2  = (const float*)d_in[12];
    const float* dt    = (const float*)d_in[13];
    const float* q_w   = (const float*)d_in[14];
    const float* k_w   = (const float*)d_in[15];
    const float* v_w   = (const float*)d_in[16];
    const float* o_w   = (const float*)d_in[17];
    const float* temp  = (const float*)d_in[18];
    const float* cu_w1 = (const float*)d_in[19];
    const float* cu_b1 = (const float*)d_in[20];
    const float* cu_w2 = (const float*)d_in[21];
    const float* cu_b2 = (const float*)d_in[22];
    const float* m_w1  = (const float*)d_in[23];
    const float* m_b1  = (const float*)d_in[24];
    const float* m_w2  = (const float*)d_in[25];
    const float* m_b2  = (const float*)d_in[26];

    float* out_z2 = (float*)d_out;
    float* out_cn = out_z2 + (size_t)NTOK * DIM;
    float* out_zb = out_cn + (size_t)NTOK * DIM;

    float* zn   = sym(g_zn);
    float* cn   = sym(g_cn);
    float* hf   = sym(g_hf);
    float* dzl  = sym(g_dzl);
    float* gh   = sym(g_gh);
    float* dz   = sym(g_dz);
    float* QKb  = sym(g_QK);
    float* Vb   = sym(g_V);
    float* attn = sym(g_attn);
    float* z1   = sym(g_z1);
    float* hcu  = sym(g_hcu);
    float* z1n  = sym(g_z1n);
    float* h4   = sym(g_h4);

    const int ND = NTOK * DIM;

    // 1. norms (fused pair)
    rms2_kernel<<<2 * NTOK, 256>>>(z, w_z, zn, conn, w_c, cn);

    // 2. vector field F(zn)
    { Seg s[1] = {{zn, DIM}};
      launch_gemm<128,1,0,true>(s, 1, f_w1, f_b1, nullptr, nullptr, nullptr,
                                hf, NTOK, 2*DIM, DIM); }
    { Seg s[2] = {{hf, 2*DIM}, {hf + DIM, 2*DIM}};
      launch_gemm<64,0,0,true>(s, 2, f_w2, f_b2, nullptr, nullptr, nullptr,
                               dzl, NTOK, DIM, 2*DIM); }

    // 3. gamma: gh = tanh([cn,dzl]@g_w1^T+b); dz = dt*(dzl + gh@g_w2^T + b)
    { Seg s[2] = {{cn, DIM}, {dzl, DIM}};
      launch_gemm<64,2,0,true>(s, 2, g_w1, g_b1, nullptr, nullptr, nullptr,
                               gh, NTOK, DIM, 2*DIM); }
    { Seg s[1] = {{gh, DIM}};
      launch_gemm<64,0,2,true>(s, 1, g_w2, g_b2, dzl, nullptr, dt,
                               dz, NTOK, DIM, DIM); }

    // 4. attention projections: Q+K merged (N=2048, W row-split), V separate
    { Seg s[2] = {{zn, DIM}, {cn, DIM}};
      launch_gemm2<128,0,0,false>(s, 2, q_w, k_w, DIM, nullptr,
                                  nullptr, nullptr, nullptr,
                                  QKb, NTOK, 2*DIM, 2*DIM); }
    { Seg s[1] = {{zn, DIM}};
      launch_gemm<64,0,0,false>(s, 1, v_w, nullptr, nullptr, nullptr, nullptr,
                                Vb, NTOK, DIM, DIM); }

    // 5. sigmoid attention (Q at cols [0,1024), K at cols [1024,2048) of g_QK)
    {
        dim3 g(SEQ / AQ, NHEAD, BATCH), b(256);
        attn_tc_kernel<<<g, b>>>(QKb, QKb + DIM, 2 * DIM, Vb, temp, attn);
    }

    // 6. z1 = z + dz + attn @ o_w^T
    { Seg s[1] = {{attn, DIM}};
      launch_gemm<64,0,3,false>(s, 1, o_w, nullptr, z, dz, nullptr,
                                z1, NTOK, DIM, DIM); }

    // 7. connection update
    { Seg s[3] = {{conn, DIM}, {z1, DIM}, {dz, DIM}};
      launch_gemm<128,1,0,true>(s, 3, cu_w1, cu_b1, nullptr, nullptr, nullptr,
                                hcu, NTOK, 2*DIM, 3*DIM); }
    { Seg s[2] = {{hcu, 2*DIM}, {hcu + DIM, 2*DIM}};
      launch_gemm<64,0,1,true>(s, 2, cu_w2, cu_b2, conn, nullptr, nullptr,
                               out_cn, NTOK, DIM, 2*DIM); }

    // 8. MLP block
    rms_kernel<<<NTOK, 256>>>(z1, w_mlp, z1n);
    { Seg s[1] = {{z1n, DIM}};
      launch_gemm<128,1,0,true>(s, 1, m_w1, m_b1, nullptr, nullptr, nullptr,
                                h4, NTOK, 4*DIM, DIM); }
    { Seg s[4] = {{h4, 4*DIM}, {h4 + DIM, 4*DIM}, {h4 + 2*DIM, 4*DIM}, {h4 + 3*DIM, 4*DIM}};
      launch_gemm<64,0,1,true>(s, 4, m_w2, m_b2, z1, nullptr, nullptr,
                               out_z2, NTOK, DIM, 4*DIM); }

    // 9. z_before passthrough
    cudaMemcpyAsync(out_zb, z, (size_t)ND * sizeof(float), cudaMemcpyDeviceToDevice);
}

// round 8
// speedup vs baseline: 1.2008x; 1.2008x over previous
#include <cuda_runtime.h>
#include <math.h>
#include <stdint.h>

#define BATCH 2
#define SEQ   2048
#define DIM   1024
#define NHEAD 16
#define HDIM  64
#define NTOK  (BATCH*SEQ)   // 4096

// ---------------------------------------------------------------------------
// Scratch
// ---------------------------------------------------------------------------
__device__ float g_zn  [NTOK*DIM];
__device__ float g_cn  [NTOK*DIM];
__device__ float g_hf  [NTOK*2*DIM];
__device__ float g_dzl [NTOK*DIM];
__device__ float g_gh  [NTOK*DIM];
__device__ float g_dz  [NTOK*DIM];
__device__ float g_QK  [NTOK*2*DIM];   // packed: cols [0,1024)=Q, [1024,2048)=K
__device__ float g_V   [NTOK*DIM];
__device__ float g_attn[NTOK*DIM];
__device__ float g_z1  [NTOK*DIM];
__device__ float g_hcu [NTOK*2*DIM];
__device__ float g_z1n [NTOK*DIM];
__device__ float g_h4  [NTOK*4*DIM];

// ---------------------------------------------------------------------------
// helpers
// ---------------------------------------------------------------------------
__device__ __forceinline__ uint32_t f2tf32(float f)
{
    uint32_t r;
    asm("cvt.rna.tf32.f32 %0, %1;" : "=r"(r) : "f"(f));
    return r;
}

__device__ __forceinline__ void mma_tf32(float* c, const uint32_t* a, const uint32_t* b)
{
    asm volatile("mma.sync.aligned.m16n8k8.row.col.f32.tf32.tf32.f32 "
                 "{%0,%1,%2,%3}, {%4,%5,%6,%7}, {%8,%9}, {%0,%1,%2,%3};"
                 : "+f"(c[0]), "+f"(c[1]), "+f"(c[2]), "+f"(c[3])
                 : "r"(a[0]), "r"(a[1]), "r"(a[2]), "r"(a[3]),
                   "r"(b[0]), "r"(b[1]));
}

// 4x (8x8 b16) ldmatrix == 4 tf32 fragments of an (8x4 b32) tile
__device__ __forceinline__ void ldsm_x4(uint32_t* r, uint32_t addr)
{
    asm volatile("ldmatrix.sync.aligned.m8n8.x4.shared.b16 {%0,%1,%2,%3}, [%4];"
                 : "=r"(r[0]), "=r"(r[1]), "=r"(r[2]), "=r"(r[3]) : "r"(addr));
}

// ---------------------------------------------------------------------------
// Fused RMSNorm pair + single RMSNorm
// ---------------------------------------------------------------------------
__global__ void rms2_kernel(const float* __restrict__ x0, const float* __restrict__ w0,
                            float* __restrict__ o0,
                            const float* __restrict__ x1, const float* __restrict__ w1,
                            float* __restrict__ o1)
{
    int rid = blockIdx.x;
    const float* x; const float* w; float* o; int row;
    if (rid < NTOK) { x = x0; w = w0; o = o0; row = rid; }
    else            { x = x1; w = w1; o = o1; row = rid - NTOK; }

    int t = threadIdx.x;
    const float4* xr = (const float4*)(x + (size_t)row * DIM);
    float4 v = xr[t];
    float ss = v.x*v.x + v.y*v.y + v.z*v.z + v.w*v.w;

    __shared__ float red[256];
    red[t] = ss;
    __syncthreads();
    for (int s = 128; s > 0; s >>= 1) {
        if (t < s) red[t] += red[t + s];
        __syncthreads();
    }
    float inv = rsqrtf(red[0] * (1.0f / DIM) + 1e-6f);
    float4 wv = ((const float4*)w)[t];
    float4 ov;
    ov.x = v.x * inv * wv.x;
    ov.y = v.y * inv * wv.y;
    ov.z = v.z * inv * wv.z;
    ov.w = v.w * inv * wv.w;
    ((float4*)(o + (size_t)row * DIM))[t] = ov;
}

__global__ void rms_kernel(const float* __restrict__ x, const float* __restrict__ w,
                           float* __restrict__ o)
{
    int row = blockIdx.x;
    int t   = threadIdx.x;
    const float4* xr = (const float4*)(x + (size_t)row * DIM);
    float4 v = xr[t];
    float ss = v.x*v.x + v.y*v.y + v.z*v.z + v.w*v.w;

    __shared__ float red[256];
    red[t] = ss;
    __syncthreads();
    for (int s = 128; s > 0; s >>= 1) {
        if (t < s) red[t] += red[t + s];
        __syncthreads();
    }
    float inv = rsqrtf(red[0] * (1.0f / DIM) + 1e-6f);
    float4 wv = ((const float4*)w)[t];
    float4 ov;
    ov.x = v.x * inv * wv.x;
    ov.y = v.y * inv * wv.y;
    ov.z = v.z * inv * wv.z;
    ov.w = v.w * inv * wv.w;
    ((float4*)(o + (size_t)row * DIM))[t] = ov;
}

// ---------------------------------------------------------------------------
// TF32 tensor-core GEMM:  C = EPI( ACT( gatherA @ W^T + bias ) )
// Block tile 128x128x32, 8 warps, warp tile 32x64.
// Loader: LDG -> cvt.rna.tf32 -> STS (register double-buffered, 2 smem stages).
// Inner loop: ldmatrix.x4 fragment loads (no LDS/CVT in the hot loop).
// A: up to 4 K-segments of width 1024 (concat fusion).
// W: row-segmented at 'wsplit' between W0 / W1 (merged QK projection).
// EPI: 0 none | 1 +res1 | 2 dt*(res1+v) | 3 v+res1+res2
// ACT: 0 none | 1 silu | 2 tanh
// ---------------------------------------------------------------------------
#define BM 128
#define BN 128
#define BK 32
#define KST 36                       // BK + 4 pad (bank-staggers LDSM rows)
#define SA (BM * KST)                // floats per stage per matrix
#define GEMM_SMEM (4 * SA * 4)       // 2 stages x 2 matrices, bytes

template<int ACT, int EPI, bool HAS_BIAS>
__global__ __launch_bounds__(256)
void gemm_tc_kernel(const float* __restrict__ p0, const float* __restrict__ p1,
                    const float* __restrict__ p2, const float* __restrict__ p3,
                    int s0, int s1, int s2, int s3,
                    const float* __restrict__ W0, const float* __restrict__ W1,
                    int wsplit,
                    const float* __restrict__ bias,
                    const float* __restrict__ res1, const float* __restrict__ res2,
                    const float* __restrict__ dtp,
                    float* __restrict__ C, int M, int N, int K)
{
    extern __shared__ float dsm[];   // [A0][A1][W0][W1]
    const uint32_t smem0 = (uint32_t)__cvta_generic_to_shared(dsm);

    const int bm = blockIdx.y * BM;
    const int bn = blockIdx.x * BN;
    const int tid  = threadIdx.x;
    const int warp = tid >> 5;
    const int lane = tid & 31;
    const int gid  = lane >> 2;
    const int tig  = lane & 3;
    const int wm   = warp >> 1;      // 0..3 -> 32-row slice
    const int wn   = warp & 1;       // 0..1 -> 64-col slice
    const int lg   = lane >> 3;      // ldmatrix group 0..3
    const int lr   = lane & 7;       // row within ldmatrix group

    const int rbase = tid >> 3;      // loader row 0..31 (+32 per it)
    const int c4    = (tid & 7) * 4; // loader float col within BK

    const float* Wb = (bn < wsplit) ? (W0 + (size_t)bn * K)
                                    : (W1 + (size_t)(bn - wsplit) * K);

    float acc[2][8][4];
    #pragma unroll
    for (int mi = 0; mi < 2; mi++)
        #pragma unroll
        for (int ni = 0; ni < 8; ni++)
            #pragma unroll
            for (int r = 0; r < 4; r++) acc[mi][ni][r] = 0.0f;

    const int KT = K / BK;

    float4 ra[4], rw[4];

    #define LDG_TILE(KT_IDX)                                                        \
    {                                                                               \
        const int gk  = (KT_IDX) * BK;                                              \
        const int seg = gk >> 10;                                                   \
        const float* sp = (seg == 0) ? p0 : (seg == 1) ? p1 : (seg == 2) ? p2 : p3; \
        const int    st = (seg == 0) ? s0 : (seg == 1) ? s1 : (seg == 2) ? s2 : s3; \
        const int    ko = (gk & 1023) + c4;                                         \
        _Pragma("unroll")                                                           \
        for (int it = 0; it < 4; it++)                                              \
            ra[it] = *(const float4*)(sp + (size_t)(bm + rbase + it * 32) * st + ko); \
        _Pragma("unroll")                                                           \
        for (int it = 0; it < 4; it++)                                              \
            rw[it] = *(const float4*)(Wb + (size_t)(rbase + it * 32) * K + gk + c4); \
    }

    #define STS_TILE(BUF)                                                           \
    {                                                                               \
        _Pragma("unroll")                                                           \
        for (int it = 0; it < 4; it++) {                                            \
            uint4 t4;                                                               \
            t4.x = f2tf32(ra[it].x); t4.y = f2tf32(ra[it].y);                       \
            t4.z = f2tf32(ra[it].z); t4.w = f2tf32(ra[it].w);                       \
            *(uint4*)(dsm + (BUF) * SA + (rbase + it * 32) * KST + c4) = t4;        \
            uint4 w4;                                                               \
            w4.x = f2tf32(rw[it].x); w4.y = f2tf32(rw[it].y);                       \
            w4.z = f2tf32(rw[it].z); w4.w = f2tf32(rw[it].w);                       \
            *(uint4*)(dsm + (2 + (BUF)) * SA + (rbase + it * 32) * KST + c4) = w4;  \
        }                                                                           \
    }

    LDG_TILE(0);
    STS_TILE(0);
    __syncthreads();

    int buf = 0;
    for (int kt = 0; kt < KT; kt++) {
        if (kt + 1 < KT) LDG_TILE(kt + 1);

        const uint32_t sAaddr = smem0 + (uint32_t)(buf * SA) * 4;
        const uint32_t sWaddr = smem0 + (uint32_t)((2 + buf) * SA) * 4;

        #pragma unroll
        for (int k0 = 0; k0 < BK; k0 += 8) {
            uint32_t afr[2][4], bq[4][4];
            #pragma unroll
            for (int mi = 0; mi < 2; mi++) {
                int row = wm * 32 + mi * 16 + (lg & 1) * 8 + lr;
                int col = k0 + (lg >> 1) * 4;
                ldsm_x4(afr[mi], sAaddr + (uint32_t)(row * KST + col) * 4);
            }
            #pragma unroll
            for (int nip = 0; nip < 4; nip++) {
                int row = wn * 64 + (2 * nip + (lg >> 1)) * 8 + lr;
                int col = k0 + (lg & 1) * 4;
                ldsm_x4(bq[nip], sWaddr + (uint32_t)(row * KST + col) * 4);
            }
            #pragma unroll
            for (int mi = 0; mi < 2; mi++)
                #pragma unroll
                for (int ni = 0; ni < 8; ni++)
                    mma_tf32(acc[mi][ni], afr[mi], &bq[ni >> 1][(ni & 1) * 2]);
        }

        if (kt + 1 < KT) STS_TILE(buf ^ 1);
        __syncthreads();
        buf ^= 1;
    }
    #undef LDG_TILE
    #undef STS_TILE

    const float dtv = (EPI == 2) ? dtp[0] : 0.0f;

    #pragma unroll
    for (int mi = 0; mi < 2; mi++) {
        int row = bm + wm * 32 + mi * 16 + gid;
        #pragma unroll
        for (int ni = 0; ni < 8; ni++) {
            int col = bn + wn * 64 + ni * 8 + 2 * tig;
            float b0 = 0.f, b1 = 0.f;
            if (HAS_BIAS) { b0 = bias[col]; b1 = bias[col + 1]; }
            #pragma unroll
            for (int half = 0; half < 2; half++) {
                int r = row + half * 8;
                float v0 = acc[mi][ni][half * 2 + 0] + b0;
                float v1 = acc[mi][ni][half * 2 + 1] + b1;
                if (ACT == 1) { v0 = v0 / (1.0f + __expf(-v0)); v1 = v1 / (1.0f + __expf(-v1)); }
                else if (ACT == 2) { v0 = tanhf(v0); v1 = tanhf(v1); }
                if (EPI == 1) {
                    const float2 rv = *(const float2*)(res1 + (size_t)r * N + col);
                    v0 += rv.x; v1 += rv.y;
                } else if (EPI == 2) {
                    const float2 rv = *(const float2*)(res1 + (size_t)r * N + col);
                    v0 = dtv * (rv.x + v0); v1 = dtv * (rv.y + v1);
                } else if (EPI == 3) {
                    const float2 ra2 = *(const float2*)(res1 + (size_t)r * N + col);
                    const float2 rb2 = *(const float2*)(res2 + (size_t)r * N + col);
                    v0 += ra2.x + rb2.x; v1 += ra2.y + rb2.y;
                }
                *(float2*)(C + (size_t)r * N + col) = make_float2(v0, v1);
            }
        }
    }
}

// ---------------------------------------------------------------------------
// Sigmoid attention on tensor cores (tf32 mma.sync flash-style).
// Q/K read from packed [NTOK, 2048] buffer (stride qstr); V/O stride DIM.
// ---------------------------------------------------------------------------
#define AQ  128
#define AKV 32

__global__ __launch_bounds__(256)
void attn_tc_kernel(const float* __restrict__ Qp, const float* __restrict__ Kp,
                    int qstr,
                    const float* __restrict__ V, const float* __restrict__ temp,
                    float* __restrict__ O)
{
    __shared__ float Ks[AKV][68];
    __shared__ float Vs[AKV][72];
    __shared__ float Ps[AQ][68];

    const int b = blockIdx.z, h = blockIdx.y;
    const int q0 = blockIdx.x * AQ;
    const int tid = threadIdx.x;
    const int warp = tid >> 5, lane = tid & 31;
    const int gid = lane >> 2, tig = lane & 3;

    const float scale = 0.125f * temp[0];
    const size_t baseq  = ((size_t)(b * SEQ + q0)) * qstr + h * HDIM;
    const size_t basek  = ((size_t)(b * SEQ)) * qstr + h * HDIM;
    const size_t basev  = ((size_t)(b * SEQ)) * DIM + h * HDIM;
    const size_t baseo  = ((size_t)(b * SEQ + q0)) * DIM + h * HDIM;

    const int r0 = warp * 16 + gid;

    uint32_t qfr[8][4];
    {
        const float* Qr0 = Qp + baseq + (size_t)r0 * qstr;
        const float* Qr1 = Qr0 + (size_t)8 * qstr;
        #pragma unroll
        for (int kc = 0; kc < 8; kc++) {
            qfr[kc][0] = f2tf32(Qr0[kc * 8 + tig    ]);
            qfr[kc][1] = f2tf32(Qr1[kc * 8 + tig    ]);
            qfr[kc][2] = f2tf32(Qr0[kc * 8 + tig + 4]);
            qfr[kc][3] = f2tf32(Qr1[kc * 8 + tig + 4]);
        }
    }

    float acc_o[8][4];
    #pragma unroll
    for (int nb = 0; nb < 8; nb++)
        #pragma unroll
        for (int r = 0; r < 4; r++) acc_o[nb][r] = 0.0f;
    float rs0 = 0.0f, rs1 = 0.0f;

    for (int m0 = 0; m0 < SEQ; m0 += AKV) {
        __syncthreads();
        #pragma unroll
        for (int it = 0; it < 2; it++) {
            int f = tid + it * 256;
            int r = f >> 4, c4 = (f & 15) * 4;
            float4 kv = *(const float4*)(Kp + basek + (size_t)(m0 + r) * qstr + c4);
            Ks[r][c4] = kv.x; Ks[r][c4 + 1] = kv.y; Ks[r][c4 + 2] = kv.z; Ks[r][c4 + 3] = kv.w;
            float4 vv = *(const float4*)(V + basev + (size_t)(m0 + r) * DIM + c4);
            Vs[r][c4] = vv.x; Vs[r][c4 + 1] = vv.y; Vs[r][c4 + 2] = vv.z; Vs[r][c4 + 3] = vv.w;
        }
        __syncthreads();

        float acc_s[4][4] = {};
        #pragma unroll
        for (int kc = 0; kc < 8; kc++) {
            uint32_t bfr[4][2];
            #pragma unroll
            for (int nb = 0; nb < 4; nb++) {
                bfr[nb][0] = f2tf32(Ks[nb * 8 + gid][kc * 8 + tig    ]);
                bfr[nb][1] = f2tf32(Ks[nb * 8 + gid][kc * 8 + tig + 4]);
            }
            #pragma unroll
            for (int nb = 0; nb < 4; nb++)
                mma_tf32(acc_s[nb], qfr[kc], bfr[nb]);
        }

        #pragma unroll
        for (int nb = 0; nb < 4; nb++) {
            float s00 = 1.0f / (1.0f + __expf(-acc_s[nb][0] * scale));
            float s01 = 1.0f / (1.0f + __expf(-acc_s[nb][1] * scale));
            float s10 = 1.0f / (1.0f + __expf(-acc_s[nb][2] * scale));
            float s11 = 1.0f / (1.0f + __expf(-acc_s[nb][3] * scale));
            rs0 += s00 + s01;
            rs1 += s10 + s11;
            *(float2*)&Ps[r0    ][nb * 8 + 2 * tig] = make_float2(s00, s01);
            *(float2*)&Ps[r0 + 8][nb * 8 + 2 * tig] = make_float2(s10, s11);
        }
        __syncwarp();

        #pragma unroll
        for (int kc = 0; kc < 4; kc++) {
            uint32_t afr[4];
            afr[0] = f2tf32(Ps[r0    ][kc * 8 + tig    ]);
            afr[1] = f2tf32(Ps[r0 + 8][kc * 8 + tig    ]);
            afr[2] = f2tf32(Ps[r0    ][kc * 8 + tig + 4]);
            afr[3] = f2tf32(Ps[r0 + 8][kc * 8 + tig + 4]);
            #pragma unroll
            for (int nb = 0; nb < 8; nb++) {
                uint32_t bfr[2];
                bfr[0] = f2tf32(Vs[kc * 8 + tig    ][nb * 8 + gid]);
                bfr[1] = f2tf32(Vs[kc * 8 + tig + 4][nb * 8 + gid]);
                mma_tf32(acc_o[nb], afr, bfr);
            }
        }
        __syncwarp();
    }

    rs0 += __shfl_xor_sync(0xffffffffu, rs0, 1);
    rs0 += __shfl_xor_sync(0xffffffffu, rs0, 2);
    rs1 += __shfl_xor_sync(0xffffffffu, rs1, 1);
    rs1 += __shfl_xor_sync(0xffffffffu, rs1, 2);
    const float inv0 = 1.0f / fmaxf(rs0, 1.0f);
    const float inv1 = 1.0f / fmaxf(rs1, 1.0f);

    float* O0 = O + baseo + (size_t)r0 * DIM;
    float* O1 = O0 + 8 * DIM;
    #pragma unroll
    for (int nb = 0; nb < 8; nb++) {
        int col = nb * 8 + 2 * tig;
        *(float2*)(O0 + col) = make_float2(acc_o[nb][0] * inv0, acc_o[nb][1] * inv0);
        *(float2*)(O1 + col) = make_float2(acc_o[nb][2] * inv1, acc_o[nb][3] * inv1);
    }
}

// ---------------------------------------------------------------------------
// Host-side dispatch
// ---------------------------------------------------------------------------
struct Seg { const float* p; int s; };

template<int ACT, int EPI, bool HAS_BIAS>
static void launch_gemm2(const Seg* seg, int nseg,
                         const float* W0, const float* W1, int wsplit,
                         const float* bias,
                         const float* res1, const float* res2, const float* dtp,
                         float* C, int M, int N, int K)
{
    cudaFuncSetAttribute(gemm_tc_kernel<ACT, EPI, HAS_BIAS>,
                         cudaFuncAttributeMaxDynamicSharedMemorySize, GEMM_SMEM);
    const float* p0 = seg[0].p;                     int s0 = seg[0].s;
    const float* p1 = (nseg > 1) ? seg[1].p : p0;   int s1 = (nseg > 1) ? seg[1].s : s0;
    const float* p2 = (nseg > 2) ? seg[2].p : p0;   int s2 = (nseg > 2) ? seg[2].s : s0;
    const float* p3 = (nseg > 3) ? seg[3].p : p0;   int s3 = (nseg > 3) ? seg[3].s : s0;
    dim3 g(N / BN, M / BM), b(256);
    gemm_tc_kernel<ACT, EPI, HAS_BIAS><<<g, b, GEMM_SMEM>>>(
        p0, p1, p2, p3, s0, s1, s2, s3, W0, W1, wsplit,
        bias, res1, res2, dtp, C, M, N, K);
}

template<int ACT, int EPI, bool HAS_BIAS>
static void launch_gemm(const Seg* seg, int nseg, const float* W, const float* bias,
                        const float* res1, const float* res2, const float* dtp,
                        float* C, int M, int N, int K)
{
    launch_gemm2<ACT, EPI, HAS_BIAS>(seg, nseg, W, W, 1 << 30,
                                     bias, res1, res2, dtp, C, M, N, K);
}

static float* sym(const void* s)
{
    void* p = nullptr;
    cudaGetSymbolAddress(&p, s);
    return (float*)p;
}

extern "C" void kernel_launch(void* const* d_in, const int* in_sizes, int n_in,
                              void* d_out, int out_size)
{
    const float* z     = (const float*)d_in[0];
    const float* conn  = (const float*)d_in[1];
    const float* w_z   = (const float*)d_in[2];
    const float* w_c   = (const float*)d_in[3];
    const float* w_mlp = (const float*)d_in[4];
    const float* f_w1  = (const float*)d_in[5];
    const float* f_b1  = (const float*)d_in[6];
    const float* f_w2  = (const float*)d_in[7];
    const float* f_b2  = (const float*)d_in[8];
    const float* g_w1  = (const float*)d_in[9];
    const float* g_b1  = (const float*)d_in[10];
    const float* g_w2  = (const float*)d_in[11];
    const float* g_b2  = (const float*)d_in[12];
    const float* dt    = (const float*)d_in[13];
    const float* q_w   = (const float*)d_in[14];
    const float* k_w   = (const float*)d_in[15];
    const float* v_w   = (const float*)d_in[16];
    const float* o_w   = (const float*)d_in[17];
    const float* temp  = (const float*)d_in[18];
    const float* cu_w1 = (const float*)d_in[19];
    const float* cu_b1 = (const float*)d_in[20];
    const float* cu_w2 = (const float*)d_in[21];
    const float* cu_b2 = (const float*)d_in[22];
    const float* m_w1  = (const float*)d_in[23];
    const float* m_b1  = (const float*)d_in[24];
    const float* m_w2  = (const float*)d_in[25];
    const float* m_b2  = (const float*)d_in[26];

    float* out_z2 = (float*)d_out;
    float* out_cn = out_z2 + (size_t)NTOK * DIM;
    float* out_zb = out_cn + (size_t)NTOK * DIM;

    float* zn   = sym(g_zn);
    float* cn   = sym(g_cn);
    float* hf   = sym(g_hf);
    float* dzl  = sym(g_dzl);
    float* gh   = sym(g_gh);
    float* dz   = sym(g_dz);
    float* QKb  = sym(g_QK);
    float* Vb   = sym(g_V);
    float* attn = sym(g_attn);
    float* z1   = sym(g_z1);
    float* hcu  = sym(g_hcu);
    float* z1n  = sym(g_z1n);
    float* h4   = sym(g_h4);

    const int ND = NTOK * DIM;

    // 1. norms (fused pair)
    rms2_kernel<<<2 * NTOK, 256>>>(z, w_z, zn, conn, w_c, cn);

    // 2. vector field F(zn)
    { Seg s[1] = {{zn, DIM}};
      launch_gemm<1,0,true>(s, 1, f_w1, f_b1, nullptr, nullptr, nullptr,
                            hf, NTOK, 2*DIM, DIM); }
    { Seg s[2] = {{hf, 2*DIM}, {hf + DIM, 2*DIM}};
      launch_gemm<0,0,true>(s, 2, f_w2, f_b2, nullptr, nullptr, nullptr,
                            dzl, NTOK, DIM, 2*DIM); }

    // 3. gamma: gh = tanh([cn,dzl]@g_w1^T+b); dz = dt*(dzl + gh@g_w2^T + b)
    { Seg s[2] = {{cn, DIM}, {dzl, DIM}};
      launch_gemm<2,0,true>(s, 2, g_w1, g_b1, nullptr, nullptr, nullptr,
                            gh, NTOK, DIM, 2*DIM); }
    { Seg s[1] = {{gh, DIM}};
      launch_gemm<0,2,true>(s, 1, g_w2, g_b2, dzl, nullptr, dt,
                            dz, NTOK, DIM, DIM); }

    // 4. attention projections: Q+K merged (N=2048, W row-split), V separate
    { Seg s[2] = {{zn, DIM}, {cn, DIM}};
      launch_gemm2<0,0,false>(s, 2, q_w, k_w, DIM, nullptr,
                              nullptr, nullptr, nullptr,
                              QKb, NTOK, 2*DIM, 2*DIM); }
    { Seg s[1] = {{zn, DIM}};
      launch_gemm<0,0,false>(s, 1, v_w, nullptr, nullptr, nullptr, nullptr,
                             Vb, NTOK, DIM, DIM); }

    // 5. sigmoid attention
    {
        dim3 g(SEQ / AQ, NHEAD, BATCH), b(256);
        attn_tc_kernel<<<g, b>>>(QKb, QKb + DIM, 2 * DIM, Vb, temp, attn);
    }

    // 6. z1 = z + dz + attn @ o_w^T
    { Seg s[1] = {{attn, DIM}};
      launch_gemm<0,3,false>(s, 1, o_w, nullptr, z, dz, nullptr,
                             z1, NTOK, DIM, DIM); }

    // 7. connection update
    { Seg s[3] = {{conn, DIM}, {z1, DIM}, {dz, DIM}};
      launch_gemm<1,0,true>(s, 3, cu_w1, cu_b1, nullptr, nullptr, nullptr,
                            hcu, NTOK, 2*DIM, 3*DIM); }
    { Seg s[2] = {{hcu, 2*DIM}, {hcu + DIM, 2*DIM}};
      launch_gemm<0,1,true>(s, 2, cu_w2, cu_b2, conn, nullptr, nullptr,
                            out_cn, NTOK, DIM, 2*DIM); }

    // 8. MLP block
    rms_kernel<<<NTOK, 256>>>(z1, w_mlp, z1n);
    { Seg s[1] = {{z1n, DIM}};
      launch_gemm<1,0,true>(s, 1, m_w1, m_b1, nullptr, nullptr, nullptr,
                            h4, NTOK, 4*DIM, DIM); }
    { Seg s[4] = {{h4, 4*DIM}, {h4 + DIM, 4*DIM}, {h4 + 2*DIM, 4*DIM}, {h4 + 3*DIM, 4*DIM}};
      launch_gemm<0,1,true>(s, 4, m_w2, m_b2, z1, nullptr, nullptr,
                            out_z2, NTOK, DIM, 4*DIM); }

    // 9. z_before passthrough
    cudaMemcpyAsync(out_zb, z, (size_t)ND * sizeof(float), cudaMemcpyDeviceToDevice);
}

// round 9
// speedup vs baseline: 1.3638x; 1.1358x over previous
#include <cuda_runtime.h>
#include <math.h>
#include <stdint.h>

#define BATCH 2
#define SEQ   2048
#define DIM   1024
#define NHEAD 16
#define HDIM  64
#define NTOK  (BATCH*SEQ)   // 4096

// ---------------------------------------------------------------------------
// Scratch
// ---------------------------------------------------------------------------
__device__ float g_zn  [NTOK*DIM];
__device__ float g_cn  [NTOK*DIM];
__device__ float g_hf  [NTOK*2*DIM];
__device__ float g_dzl [NTOK*DIM];
__device__ float g_gh  [NTOK*DIM];
__device__ float g_dz  [NTOK*DIM];
__device__ float g_QK  [NTOK*2*DIM];   // packed: cols [0,1024)=Q, [1024,2048)=K
__device__ float g_V   [NTOK*DIM];
__device__ float g_attn[NTOK*DIM];
__device__ float g_z1  [NTOK*DIM];
__device__ float g_hcu [NTOK*2*DIM];
__device__ float g_z1n [NTOK*DIM];
__device__ float g_h4  [NTOK*4*DIM];

// ---------------------------------------------------------------------------
// helpers
// ---------------------------------------------------------------------------
__device__ __forceinline__ uint32_t f2tf32(float f)
{
    uint32_t r;
    asm("cvt.rna.tf32.f32 %0, %1;" : "=r"(r) : "f"(f));
    return r;
}

__device__ __forceinline__ void mma_tf32(float* c, const uint32_t* a, const uint32_t* b)
{
    asm volatile("mma.sync.aligned.m16n8k8.row.col.f32.tf32.tf32.f32 "
                 "{%0,%1,%2,%3}, {%4,%5,%6,%7}, {%8,%9}, {%0,%1,%2,%3};"
                 : "+f"(c[0]), "+f"(c[1]), "+f"(c[2]), "+f"(c[3])
                 : "r"(a[0]), "r"(a[1]), "r"(a[2]), "r"(a[3]),
                   "r"(b[0]), "r"(b[1]));
}

// 4x (8x8 b16) ldmatrix == 4 tf32 fragments of an (8x4 b32) tile
__device__ __forceinline__ void ldsm_x4(uint32_t* r, uint32_t addr)
{
    asm volatile("ldmatrix.sync.aligned.m8n8.x4.shared.b16 {%0,%1,%2,%3}, [%4];"
                 : "=r"(r[0]), "=r"(r[1]), "=r"(r[2]), "=r"(r[3]) : "r"(addr));
}

// ---------------------------------------------------------------------------
// Fused RMSNorm pair + single RMSNorm
// ---------------------------------------------------------------------------
__global__ void rms2_kernel(const float* __restrict__ x0, const float* __restrict__ w0,
                            float* __restrict__ o0,
                            const float* __restrict__ x1, const float* __restrict__ w1,
                            float* __restrict__ o1)
{
    int rid = blockIdx.x;
    const float* x; const float* w; float* o; int row;
    if (rid < NTOK) { x = x0; w = w0; o = o0; row = rid; }
    else            { x = x1; w = w1; o = o1; row = rid - NTOK; }

    int t = threadIdx.x;
    const float4* xr = (const float4*)(x + (size_t)row * DIM);
    float4 v = xr[t];
    float ss = v.x*v.x + v.y*v.y + v.z*v.z + v.w*v.w;

    __shared__ float red[256];
    red[t] = ss;
    __syncthreads();
    for (int s = 128; s > 0; s >>= 1) {
        if (t < s) red[t] += red[t + s];
        __syncthreads();
    }
    float inv = rsqrtf(red[0] * (1.0f / DIM) + 1e-6f);
    float4 wv = ((const float4*)w)[t];
    float4 ov;
    ov.x = v.x * inv * wv.x;
    ov.y = v.y * inv * wv.y;
    ov.z = v.z * inv * wv.z;
    ov.w = v.w * inv * wv.w;
    ((float4*)(o + (size_t)row * DIM))[t] = ov;
}

__global__ void rms_kernel(const float* __restrict__ x, const float* __restrict__ w,
                           float* __restrict__ o)
{
    int row = blockIdx.x;
    int t   = threadIdx.x;
    const float4* xr = (const float4*)(x + (size_t)row * DIM);
    float4 v = xr[t];
    float ss = v.x*v.x + v.y*v.y + v.z*v.z + v.w*v.w;

    __shared__ float red[256];
    red[t] = ss;
    __syncthreads();
    for (int s = 128; s > 0; s >>= 1) {
        if (t < s) red[t] += red[t + s];
        __syncthreads();
    }
    float inv = rsqrtf(red[0] * (1.0f / DIM) + 1e-6f);
    float4 wv = ((const float4*)w)[t];
    float4 ov;
    ov.x = v.x * inv * wv.x;
    ov.y = v.y * inv * wv.y;
    ov.z = v.z * inv * wv.z;
    ov.w = v.w * inv * wv.w;
    ((float4*)(o + (size_t)row * DIM))[t] = ov;
}

// ---------------------------------------------------------------------------
// TF32 tensor-core GEMM:  C = EPI( ACT( gatherA @ W^T + bias ) )
// Block tile 128x128x32, 8 warps, warp tile 32x64.
// Loader: LDG -> cvt.rna.tf32 -> STS (register double-buffered, 2 smem stages).
// Inner loop: ldmatrix.x4 fragment loads.
// EPI: 0 none | 1 +res1 | 2 dt*(res1+v) | 3 v+res1+res2
// ACT: 0 none | 1 silu | 2 tanh
// ---------------------------------------------------------------------------
#define BM 128
#define BN 128
#define BK 32
#define KST 36
#define SA (BM * KST)
#define GEMM_SMEM (4 * SA * 4)

template<int ACT, int EPI, bool HAS_BIAS>
__global__ __launch_bounds__(256)
void gemm_tc_kernel(const float* __restrict__ p0, const float* __restrict__ p1,
                    const float* __restrict__ p2, const float* __restrict__ p3,
                    int s0, int s1, int s2, int s3,
                    const float* __restrict__ W0, const float* __restrict__ W1,
                    int wsplit,
                    const float* __restrict__ bias,
                    const float* __restrict__ res1, const float* __restrict__ res2,
                    const float* __restrict__ dtp,
                    float* __restrict__ C, int M, int N, int K)
{
    extern __shared__ float dsm[];   // [A0][A1][W0][W1]
    const uint32_t smem0 = (uint32_t)__cvta_generic_to_shared(dsm);

    const int bm = blockIdx.y * BM;
    const int bn = blockIdx.x * BN;
    const int tid  = threadIdx.x;
    const int warp = tid >> 5;
    const int lane = tid & 31;
    const int gid  = lane >> 2;
    const int tig  = lane & 3;
    const int wm   = warp >> 1;
    const int wn   = warp & 1;
    const int lg   = lane >> 3;
    const int lr   = lane & 7;

    const int rbase = tid >> 3;
    const int c4    = (tid & 7) * 4;

    const float* Wb = (bn < wsplit) ? (W0 + (size_t)bn * K)
                                    : (W1 + (size_t)(bn - wsplit) * K);

    float acc[2][8][4];
    #pragma unroll
    for (int mi = 0; mi < 2; mi++)
        #pragma unroll
        for (int ni = 0; ni < 8; ni++)
            #pragma unroll
            for (int r = 0; r < 4; r++) acc[mi][ni][r] = 0.0f;

    const int KT = K / BK;

    float4 ra[4], rw[4];

    #define LDG_TILE(KT_IDX)                                                        \
    {                                                                               \
        const int gk  = (KT_IDX) * BK;                                              \
        const int seg = gk >> 10;                                                   \
        const float* sp = (seg == 0) ? p0 : (seg == 1) ? p1 : (seg == 2) ? p2 : p3; \
        const int    st = (seg == 0) ? s0 : (seg == 1) ? s1 : (seg == 2) ? s2 : s3; \
        const int    ko = (gk & 1023) + c4;                                         \
        _Pragma("unroll")                                                           \
        for (int it = 0; it < 4; it++)                                              \
            ra[it] = *(const float4*)(sp + (size_t)(bm + rbase + it * 32) * st + ko); \
        _Pragma("unroll")                                                           \
        for (int it = 0; it < 4; it++)                                              \
            rw[it] = *(const float4*)(Wb + (size_t)(rbase + it * 32) * K + gk + c4); \
    }

    #define STS_TILE(BUF)                                                           \
    {                                                                               \
        _Pragma("unroll")                                                           \
        for (int it = 0; it < 4; it++) {                                            \
            uint4 t4;                                                               \
            t4.x = f2tf32(ra[it].x); t4.y = f2tf32(ra[it].y);                       \
            t4.z = f2tf32(ra[it].z); t4.w = f2tf32(ra[it].w);                       \
            *(uint4*)(dsm + (BUF) * SA + (rbase + it * 32) * KST + c4) = t4;        \
            uint4 w4;                                                               \
            w4.x = f2tf32(rw[it].x); w4.y = f2tf32(rw[it].y);                       \
            w4.z = f2tf32(rw[it].z); w4.w = f2tf32(rw[it].w);                       \
            *(uint4*)(dsm + (2 + (BUF)) * SA + (rbase + it * 32) * KST + c4) = w4;  \
        }                                                                           \
    }

    LDG_TILE(0);
    STS_TILE(0);
    __syncthreads();

    int buf = 0;
    for (int kt = 0; kt < KT; kt++) {
        if (kt + 1 < KT) LDG_TILE(kt + 1);

        const uint32_t sAaddr = smem0 + (uint32_t)(buf * SA) * 4;
        const uint32_t sWaddr = smem0 + (uint32_t)((2 + buf) * SA) * 4;

        #pragma unroll
        for (int k0 = 0; k0 < BK; k0 += 8) {
            uint32_t afr[2][4], bq[4][4];
            #pragma unroll
            for (int mi = 0; mi < 2; mi++) {
                int row = wm * 32 + mi * 16 + (lg & 1) * 8 + lr;
                int col = k0 + (lg >> 1) * 4;
                ldsm_x4(afr[mi], sAaddr + (uint32_t)(row * KST + col) * 4);
            }
            #pragma unroll
            for (int nip = 0; nip < 4; nip++) {
                int row = wn * 64 + (2 * nip + (lg >> 1)) * 8 + lr;
                int col = k0 + (lg & 1) * 4;
                ldsm_x4(bq[nip], sWaddr + (uint32_t)(row * KST + col) * 4);
            }
            #pragma unroll
            for (int mi = 0; mi < 2; mi++)
                #pragma unroll
                for (int ni = 0; ni < 8; ni++)
                    mma_tf32(acc[mi][ni], afr[mi], &bq[ni >> 1][(ni & 1) * 2]);
        }

        if (kt + 1 < KT) STS_TILE(buf ^ 1);
        __syncthreads();
        buf ^= 1;
    }
    #undef LDG_TILE
    #undef STS_TILE

    const float dtv = (EPI == 2) ? dtp[0] : 0.0f;

    #pragma unroll
    for (int mi = 0; mi < 2; mi++) {
        int row = bm + wm * 32 + mi * 16 + gid;
        #pragma unroll
        for (int ni = 0; ni < 8; ni++) {
            int col = bn + wn * 64 + ni * 8 + 2 * tig;
            float b0 = 0.f, b1 = 0.f;
            if (HAS_BIAS) { b0 = bias[col]; b1 = bias[col + 1]; }
            #pragma unroll
            for (int half = 0; half < 2; half++) {
                int r = row + half * 8;
                float v0 = acc[mi][ni][half * 2 + 0] + b0;
                float v1 = acc[mi][ni][half * 2 + 1] + b1;
                if (ACT == 1) { v0 = v0 / (1.0f + __expf(-v0)); v1 = v1 / (1.0f + __expf(-v1)); }
                else if (ACT == 2) { v0 = tanhf(v0); v1 = tanhf(v1); }
                if (EPI == 1) {
                    const float2 rv = *(const float2*)(res1 + (size_t)r * N + col);
                    v0 += rv.x; v1 += rv.y;
                } else if (EPI == 2) {
                    const float2 rv = *(const float2*)(res1 + (size_t)r * N + col);
                    v0 = dtv * (rv.x + v0); v1 = dtv * (rv.y + v1);
                } else if (EPI == 3) {
                    const float2 ra2 = *(const float2*)(res1 + (size_t)r * N + col);
                    const float2 rb2 = *(const float2*)(res2 + (size_t)r * N + col);
                    v0 += ra2.x + rb2.x; v1 += ra2.y + rb2.y;
                }
                *(float2*)(C + (size_t)r * N + col) = make_float2(v0, v1);
            }
        }
    }
}

// ---------------------------------------------------------------------------
// Sigmoid attention on tensor cores (tf32 mma.sync flash-style).
// ---------------------------------------------------------------------------
#define AQ  128
#define AKV 32

__global__ __launch_bounds__(256)
void attn_tc_kernel(const float* __restrict__ Qp, const float* __restrict__ Kp,
                    int qstr,
                    const float* __restrict__ V, const float* __restrict__ temp,
                    float* __restrict__ O)
{
    __shared__ float Ks[AKV][68];
    __shared__ float Vs[AKV][72];
    __shared__ float Ps[AQ][68];

    const int b = blockIdx.z, h = blockIdx.y;
    const int q0 = blockIdx.x * AQ;
    const int tid = threadIdx.x;
    const int warp = tid >> 5, lane = tid & 31;
    const int gid = lane >> 2, tig = lane & 3;

    const float scale = 0.125f * temp[0];
    const size_t baseq  = ((size_t)(b * SEQ + q0)) * qstr + h * HDIM;
    const size_t basek  = ((size_t)(b * SEQ)) * qstr + h * HDIM;
    const size_t basev  = ((size_t)(b * SEQ)) * DIM + h * HDIM;
    const size_t baseo  = ((size_t)(b * SEQ + q0)) * DIM + h * HDIM;

    const int r0 = warp * 16 + gid;

    uint32_t qfr[8][4];
    {
        const float* Qr0 = Qp + baseq + (size_t)r0 * qstr;
        const float* Qr1 = Qr0 + (size_t)8 * qstr;
        #pragma unroll
        for (int kc = 0; kc < 8; kc++) {
            qfr[kc][0] = f2tf32(Qr0[kc * 8 + tig    ]);
            qfr[kc][1] = f2tf32(Qr1[kc * 8 + tig    ]);
            qfr[kc][2] = f2tf32(Qr0[kc * 8 + tig + 4]);
            qfr[kc][3] = f2tf32(Qr1[kc * 8 + tig + 4]);
        }
    }

    float acc_o[8][4];
    #pragma unroll
    for (int nb = 0; nb < 8; nb++)
        #pragma unroll
        for (int r = 0; r < 4; r++) acc_o[nb][r] = 0.0f;
    float rs0 = 0.0f, rs1 = 0.0f;

    for (int m0 = 0; m0 < SEQ; m0 += AKV) {
        __syncthreads();
        #pragma unroll
        for (int it = 0; it < 2; it++) {
            int f = tid + it * 256;
            int r = f >> 4, c4 = (f & 15) * 4;
            float4 kv = *(const float4*)(Kp + basek + (size_t)(m0 + r) * qstr + c4);
            Ks[r][c4] = kv.x; Ks[r][c4 + 1] = kv.y; Ks[r][c4 + 2] = kv.z; Ks[r][c4 + 3] = kv.w;
            float4 vv = *(const float4*)(V + basev + (size_t)(m0 + r) * DIM + c4);
            Vs[r][c4] = vv.x; Vs[r][c4 + 1] = vv.y; Vs[r][c4 + 2] = vv.z; Vs[r][c4 + 3] = vv.w;
        }
        __syncthreads();

        float acc_s[4][4] = {};
        #pragma unroll
        for (int kc = 0; kc < 8; kc++) {
            uint32_t bfr[4][2];
            #pragma unroll
            for (int nb = 0; nb < 4; nb++) {
                bfr[nb][0] = f2tf32(Ks[nb * 8 + gid][kc * 8 + tig    ]);
                bfr[nb][1] = f2tf32(Ks[nb * 8 + gid][kc * 8 + tig + 4]);
            }
            #pragma unroll
            for (int nb = 0; nb < 4; nb++)
                mma_tf32(acc_s[nb], qfr[kc], bfr[nb]);
        }

        #pragma unroll
        for (int nb = 0; nb < 4; nb++) {
            float s00 = 1.0f / (1.0f + __expf(-acc_s[nb][0] * scale));
            float s01 = 1.0f / (1.0f + __expf(-acc_s[nb][1] * scale));
            float s10 = 1.0f / (1.0f + __expf(-acc_s[nb][2] * scale));
            float s11 = 1.0f / (1.0f + __expf(-acc_s[nb][3] * scale));
            rs0 += s00 + s01;
            rs1 += s10 + s11;
            *(float2*)&Ps[r0    ][nb * 8 + 2 * tig] = make_float2(s00, s01);
            *(float2*)&Ps[r0 + 8][nb * 8 + 2 * tig] = make_float2(s10, s11);
        }
        __syncwarp();

        #pragma unroll
        for (int kc = 0; kc < 4; kc++) {
            uint32_t afr[4];
            afr[0] = f2tf32(Ps[r0    ][kc * 8 + tig    ]);
            afr[1] = f2tf32(Ps[r0 + 8][kc * 8 + tig    ]);
            afr[2] = f2tf32(Ps[r0    ][kc * 8 + tig + 4]);
            afr[3] = f2tf32(Ps[r0 + 8][kc * 8 + tig + 4]);
            #pragma unroll
            for (int nb = 0; nb < 8; nb++) {
                uint32_t bfr[2];
                bfr[0] = f2tf32(Vs[kc * 8 + tig    ][nb * 8 + gid]);
                bfr[1] = f2tf32(Vs[kc * 8 + tig + 4][nb * 8 + gid]);
                mma_tf32(acc_o[nb], afr, bfr);
            }
        }
        __syncwarp();
    }

    rs0 += __shfl_xor_sync(0xffffffffu, rs0, 1);
    rs0 += __shfl_xor_sync(0xffffffffu, rs0, 2);
    rs1 += __shfl_xor_sync(0xffffffffu, rs1, 1);
    rs1 += __shfl_xor_sync(0xffffffffu, rs1, 2);
    const float inv0 = 1.0f / fmaxf(rs0, 1.0f);
    const float inv1 = 1.0f / fmaxf(rs1, 1.0f);

    float* O0 = O + baseo + (size_t)r0 * DIM;
    float* O1 = O0 + 8 * DIM;
    #pragma unroll
    for (int nb = 0; nb < 8; nb++) {
        int col = nb * 8 + 2 * tig;
        *(float2*)(O0 + col) = make_float2(acc_o[nb][0] * inv0, acc_o[nb][1] * inv0);
        *(float2*)(O1 + col) = make_float2(acc_o[nb][2] * inv1, acc_o[nb][3] * inv1);
    }
}

// ---------------------------------------------------------------------------
// Host-side dispatch
// ---------------------------------------------------------------------------
struct Seg { const float* p; int s; };

template<int ACT, int EPI, bool HAS_BIAS>
static void launch_gemm2(cudaStream_t st, const Seg* seg, int nseg,
                         const float* W0, const float* W1, int wsplit,
                         const float* bias,
                         const float* res1, const float* res2, const float* dtp,
                         float* C, int M, int N, int K)
{
    cudaFuncSetAttribute(gemm_tc_kernel<ACT, EPI, HAS_BIAS>,
                         cudaFuncAttributeMaxDynamicSharedMemorySize, GEMM_SMEM);
    const float* p0 = seg[0].p;                     int s0 = seg[0].s;
    const float* p1 = (nseg > 1) ? seg[1].p : p0;   int s1 = (nseg > 1) ? seg[1].s : s0;
    const float* p2 = (nseg > 2) ? seg[2].p : p0;   int s2 = (nseg > 2) ? seg[2].s : s0;
    const float* p3 = (nseg > 3) ? seg[3].p : p0;   int s3 = (nseg > 3) ? seg[3].s : s0;
    dim3 g(N / BN, M / BM), b(256);
    gemm_tc_kernel<ACT, EPI, HAS_BIAS><<<g, b, GEMM_SMEM, st>>>(
        p0, p1, p2, p3, s0, s1, s2, s3, W0, W1, wsplit,
        bias, res1, res2, dtp, C, M, N, K);
}

template<int ACT, int EPI, bool HAS_BIAS>
static void launch_gemm(cudaStream_t st, const Seg* seg, int nseg,
                        const float* W, const float* bias,
                        const float* res1, const float* res2, const float* dtp,
                        float* C, int M, int N, int K)
{
    launch_gemm2<ACT, EPI, HAS_BIAS>(st, seg, nseg, W, W, 1 << 30,
                                     bias, res1, res2, dtp, C, M, N, K);
}

static float* sym(const void* s)
{
    void* p = nullptr;
    cudaGetSymbolAddress(&p, s);
    return (float*)p;
}

extern "C" void kernel_launch(void* const* d_in, const int* in_sizes, int n_in,
                              void* d_out, int out_size)
{
    const float* z     = (const float*)d_in[0];
    const float* conn  = (const float*)d_in[1];
    const float* w_z   = (const float*)d_in[2];
    const float* w_c   = (const float*)d_in[3];
    const float* w_mlp = (const float*)d_in[4];
    const float* f_w1  = (const float*)d_in[5];
    const float* f_b1  = (const float*)d_in[6];
    const float* f_w2  = (const float*)d_in[7];
    const float* f_b2  = (const float*)d_in[8];
    const float* g_w1  = (const float*)d_in[9];
    const float* g_b1  = (const float*)d_in[10];
    const float* g_w2  = (const float*)d_in[11];
    const float* g_b2  = (const float*)d_in[12];
    const float* dt    = (const float*)d_in[13];
    const float* q_w   = (const float*)d_in[14];
    const float* k_w   = (const float*)d_in[15];
    const float* v_w   = (const float*)d_in[16];
    const float* o_w   = (const float*)d_in[17];
    const float* temp  = (const float*)d_in[18];
    const float* cu_w1 = (const float*)d_in[19];
    const float* cu_b1 = (const float*)d_in[20];
    const float* cu_w2 = (const float*)d_in[21];
    const float* cu_b2 = (const float*)d_in[22];
    const float* m_w1  = (const float*)d_in[23];
    const float* m_b1  = (const float*)d_in[24];
    const float* m_w2  = (const float*)d_in[25];
    const float* m_b2  = (const float*)d_in[26];

    float* out_z2 = (float*)d_out;
    float* out_cn = out_z2 + (size_t)NTOK * DIM;
    float* out_zb = out_cn + (size_t)NTOK * DIM;

    float* zn   = sym(g_zn);
    float* cn   = sym(g_cn);
    float* hf   = sym(g_hf);
    float* dzl  = sym(g_dzl);
    float* gh   = sym(g_gh);
    float* dz   = sym(g_dz);
    float* QKb  = sym(g_QK);
    float* Vb   = sym(g_V);
    float* attn = sym(g_attn);
    float* z1   = sym(g_z1);
    float* hcu  = sym(g_hcu);
    float* z1n  = sym(g_z1n);
    float* h4   = sym(g_h4);

    const int ND = NTOK * DIM;

    // Side stream + events (created once; every call performs identical work)
    static cudaStream_t s2 = nullptr;
    static cudaEvent_t evF1 = nullptr, evJ1 = nullptr, evF2 = nullptr, evJ2 = nullptr;
    if (!s2) {
        cudaStreamCreateWithFlags(&s2, cudaStreamNonBlocking);
        cudaEventCreateWithFlags(&evF1, cudaEventDisableTiming);
        cudaEventCreateWithFlags(&evJ1, cudaEventDisableTiming);
        cudaEventCreateWithFlags(&evF2, cudaEventDisableTiming);
        cudaEventCreateWithFlags(&evJ2, cudaEventDisableTiming);
    }
    cudaStream_t s0 = 0;   // default (captured) stream

    // 1. norms (fused pair) on main stream
    rms2_kernel<<<2 * NTOK, 256, 0, s0>>>(z, w_z, zn, conn, w_c, cn);

    // ---- fork 1: chain B (QK, V, attention) on s2; chain A (f/g) on s0 ----
    cudaEventRecord(evF1, s0);
    cudaStreamWaitEvent(s2, evF1, 0);

    // chain B (s2): z_before copy + projections + attention
    cudaMemcpyAsync(out_zb, z, (size_t)ND * sizeof(float),
                    cudaMemcpyDeviceToDevice, s2);
    { Seg s[2] = {{zn, DIM}, {cn, DIM}};
      launch_gemm2<0,0,false>(s2, s, 2, q_w, k_w, DIM, nullptr,
                              nullptr, nullptr, nullptr,
                              QKb, NTOK, 2*DIM, 2*DIM); }
    { Seg s[1] = {{zn, DIM}};
      launch_gemm<0,0,false>(s2, s, 1, v_w, nullptr, nullptr, nullptr, nullptr,
                             Vb, NTOK, DIM, DIM); }
    {
        dim3 g(SEQ / AQ, NHEAD, BATCH), b(256);
        attn_tc_kernel<<<g, b, 0, s2>>>(QKb, QKb + DIM, 2 * DIM, Vb, temp, attn);
    }
    cudaEventRecord(evJ1, s2);

    // chain A (s0): vector field + gamma
    { Seg s[1] = {{zn, DIM}};
      launch_gemm<1,0,true>(s0, s, 1, f_w1, f_b1, nullptr, nullptr, nullptr,
                            hf, NTOK, 2*DIM, DIM); }
    { Seg s[2] = {{hf, 2*DIM}, {hf + DIM, 2*DIM}};
      launch_gemm<0,0,true>(s0, s, 2, f_w2, f_b2, nullptr, nullptr, nullptr,
                            dzl, NTOK, DIM, 2*DIM); }
    { Seg s[2] = {{cn, DIM}, {dzl, DIM}};
      launch_gemm<2,0,true>(s0, s, 2, g_w1, g_b1, nullptr, nullptr, nullptr,
                            gh, NTOK, DIM, 2*DIM); }
    { Seg s[1] = {{gh, DIM}};
      launch_gemm<0,2,true>(s0, s, 1, g_w2, g_b2, dzl, nullptr, dt,
                            dz, NTOK, DIM, DIM); }

    // ---- join 1: o_w needs attn (B) and dz (A) ----
    cudaStreamWaitEvent(s0, evJ1, 0);

    // 6. z1 = z + dz + attn @ o_w^T
    { Seg s[1] = {{attn, DIM}};
      launch_gemm<0,3,false>(s0, s, 1, o_w, nullptr, z, dz, nullptr,
                             z1, NTOK, DIM, DIM); }

    // ---- fork 2: chain C (connection update) on s2; chain D (MLP) on s0 ----
    cudaEventRecord(evF2, s0);
    cudaStreamWaitEvent(s2, evF2, 0);

    // chain C (s2): conn_new
    { Seg s[3] = {{conn, DIM}, {z1, DIM}, {dz, DIM}};
      launch_gemm<1,0,true>(s2, s, 3, cu_w1, cu_b1, nullptr, nullptr, nullptr,
                            hcu, NTOK, 2*DIM, 3*DIM); }
    { Seg s[2] = {{hcu, 2*DIM}, {hcu + DIM, 2*DIM}};
      launch_gemm<0,1,true>(s2, s, 2, cu_w2, cu_b2, conn, nullptr, nullptr,
                            out_cn, NTOK, DIM, 2*DIM); }
    cudaEventRecord(evJ2, s2);

    // chain D (s0): MLP block
    rms_kernel<<<NTOK, 256, 0, s0>>>(z1, w_mlp, z1n);
    { Seg s[1] = {{z1n, DIM}};
      launch_gemm<1,0,true>(s0, s, 1, m_w1, m_b1, nullptr, nullptr, nullptr,
                            h4, NTOK, 4*DIM, DIM); }
    { Seg s[4] = {{h4, 4*DIM}, {h4 + DIM, 4*DIM}, {h4 + 2*DIM, 4*DIM}, {h4 + 3*DIM, 4*DIM}};
      launch_gemm<0,1,true>(s0, s, 4, m_w2, m_b2, z1, nullptr, nullptr,
                            out_z2, NTOK, DIM, 4*DIM); }

    // ---- join 2: everything back on the captured stream ----
    cudaStreamWaitEvent(s0, evJ2, 0);
}

// round 10
// speedup vs baseline: 1.4512x; 1.0641x over previous
#include <cuda_runtime.h>
#include <math.h>
#include <stdint.h>

#define BATCH 2
#define SEQ   2048
#define DIM   1024
#define NHEAD 16
#define HDIM  64
#define NTOK  (BATCH*SEQ)   // 4096

// ---------------------------------------------------------------------------
// Scratch
// ---------------------------------------------------------------------------
__device__ float g_zn  [NTOK*DIM];
__device__ float g_cn  [NTOK*DIM];
__device__ float g_hf  [NTOK*2*DIM];
__device__ float g_dzl [NTOK*DIM];
__device__ float g_gh  [NTOK*DIM];
__device__ float g_dz  [NTOK*DIM];
__device__ float g_QK  [NTOK*2*DIM];   // packed: cols [0,1024)=Q, [1024,2048)=K
__device__ float g_V   [NTOK*DIM];
__device__ float g_attn[NTOK*DIM];
__device__ float g_z1  [NTOK*DIM];
__device__ float g_hcu [NTOK*2*DIM];
__device__ float g_z1n [NTOK*DIM];
__device__ float g_h4  [NTOK*4*DIM];

// ---------------------------------------------------------------------------
// helpers
// ---------------------------------------------------------------------------
__device__ __forceinline__ uint32_t f2tf32(float f)
{
    uint32_t r;
    asm("cvt.rna.tf32.f32 %0, %1;" : "=r"(r) : "f"(f));
    return r;
}

__device__ __forceinline__ float tanh_fast(float x)
{
    float y;
    asm("tanh.approx.f32 %0, %1;" : "=f"(y) : "f"(x));
    return y;
}

__device__ __forceinline__ void mma_tf32(float* c, const uint32_t* a, const uint32_t* b)
{
    asm volatile("mma.sync.aligned.m16n8k8.row.col.f32.tf32.tf32.f32 "
                 "{%0,%1,%2,%3}, {%4,%5,%6,%7}, {%8,%9}, {%0,%1,%2,%3};"
                 : "+f"(c[0]), "+f"(c[1]), "+f"(c[2]), "+f"(c[3])
                 : "r"(a[0]), "r"(a[1]), "r"(a[2]), "r"(a[3]),
                   "r"(b[0]), "r"(b[1]));
}

// 4x (8x8 b16) ldmatrix == 4 tf32 fragments of an (8x4 b32) tile
__device__ __forceinline__ void ldsm_x4(uint32_t* r, uint32_t addr)
{
    asm volatile("ldmatrix.sync.aligned.m8n8.x4.shared.b16 {%0,%1,%2,%3}, [%4];"
                 : "=r"(r[0]), "=r"(r[1]), "=r"(r[2]), "=r"(r[3]) : "r"(addr));
}

// ---------------------------------------------------------------------------
// Fused RMSNorm pair + single RMSNorm
// ---------------------------------------------------------------------------
__global__ void rms2_kernel(const float* __restrict__ x0, const float* __restrict__ w0,
                            float* __restrict__ o0,
                            const float* __restrict__ x1, const float* __restrict__ w1,
                            float* __restrict__ o1)
{
    int rid = blockIdx.x;
    const float* x; const float* w; float* o; int row;
    if (rid < NTOK) { x = x0; w = w0; o = o0; row = rid; }
    else            { x = x1; w = w1; o = o1; row = rid - NTOK; }

    int t = threadIdx.x;
    const float4* xr = (const float4*)(x + (size_t)row * DIM);
    float4 v = xr[t];
    float ss = v.x*v.x + v.y*v.y + v.z*v.z + v.w*v.w;

    __shared__ float red[256];
    red[t] = ss;
    __syncthreads();
    for (int s = 128; s > 0; s >>= 1) {
        if (t < s) red[t] += red[t + s];
        __syncthreads();
    }
    float inv = rsqrtf(red[0] * (1.0f / DIM) + 1e-6f);
    float4 wv = ((const float4*)w)[t];
    float4 ov;
    ov.x = v.x * inv * wv.x;
    ov.y = v.y * inv * wv.y;
    ov.z = v.z * inv * wv.z;
    ov.w = v.w * inv * wv.w;
    ((float4*)(o + (size_t)row * DIM))[t] = ov;
}

__global__ void rms_kernel(const float* __restrict__ x, const float* __restrict__ w,
                           float* __restrict__ o)
{
    int row = blockIdx.x;
    int t   = threadIdx.x;
    const float4* xr = (const float4*)(x + (size_t)row * DIM);
    float4 v = xr[t];
    float ss = v.x*v.x + v.y*v.y + v.z*v.z + v.w*v.w;

    __shared__ float red[256];
    red[t] = ss;
    __syncthreads();
    for (int s = 128; s > 0; s >>= 1) {
        if (t < s) red[t] += red[t + s];
        __syncthreads();
    }
    float inv = rsqrtf(red[0] * (1.0f / DIM) + 1e-6f);
    float4 wv = ((const float4*)w)[t];
    float4 ov;
    ov.x = v.x * inv * wv.x;
    ov.y = v.y * inv * wv.y;
    ov.z = v.z * inv * wv.z;
    ov.w = v.w * inv * wv.w;
    ((float4*)(o + (size_t)row * DIM))[t] = ov;
}

// ---------------------------------------------------------------------------
// TF32 tensor-core GEMM (unchanged from R8/R9)
// ---------------------------------------------------------------------------
#define BM 128
#define BN 128
#define BK 32
#define KST 36
#define SA (BM * KST)
#define GEMM_SMEM (4 * SA * 4)

template<int ACT, int EPI, bool HAS_BIAS>
__global__ __launch_bounds__(256)
void gemm_tc_kernel(const float* __restrict__ p0, const float* __restrict__ p1,
                    const float* __restrict__ p2, const float* __restrict__ p3,
                    int s0, int s1, int s2, int s3,
                    const float* __restrict__ W0, const float* __restrict__ W1,
                    int wsplit,
                    const float* __restrict__ bias,
                    const float* __restrict__ res1, const float* __restrict__ res2,
                    const float* __restrict__ dtp,
                    float* __restrict__ C, int M, int N, int K)
{
    extern __shared__ float dsm[];   // [A0][A1][W0][W1]
    const uint32_t smem0 = (uint32_t)__cvta_generic_to_shared(dsm);

    const int bm = blockIdx.y * BM;
    const int bn = blockIdx.x * BN;
    const int tid  = threadIdx.x;
    const int warp = tid >> 5;
    const int lane = tid & 31;
    const int gid  = lane >> 2;
    const int tig  = lane & 3;
    const int wm   = warp >> 1;
    const int wn   = warp & 1;
    const int lg   = lane >> 3;
    const int lr   = lane & 7;

    const int rbase = tid >> 3;
    const int c4    = (tid & 7) * 4;

    const float* Wb = (bn < wsplit) ? (W0 + (size_t)bn * K)
                                    : (W1 + (size_t)(bn - wsplit) * K);

    float acc[2][8][4];
    #pragma unroll
    for (int mi = 0; mi < 2; mi++)
        #pragma unroll
        for (int ni = 0; ni < 8; ni++)
            #pragma unroll
            for (int r = 0; r < 4; r++) acc[mi][ni][r] = 0.0f;

    const int KT = K / BK;

    float4 ra[4], rw[4];

    #define LDG_TILE(KT_IDX)                                                        \
    {                                                                               \
        const int gk  = (KT_IDX) * BK;                                              \
        const int seg = gk >> 10;                                                   \
        const float* sp = (seg == 0) ? p0 : (seg == 1) ? p1 : (seg == 2) ? p2 : p3; \
        const int    st = (seg == 0) ? s0 : (seg == 1) ? s1 : (seg == 2) ? s2 : s3; \
        const int    ko = (gk & 1023) + c4;                                         \
        _Pragma("unroll")                                                           \
        for (int it = 0; it < 4; it++)                                              \
            ra[it] = *(const float4*)(sp + (size_t)(bm + rbase + it * 32) * st + ko); \
        _Pragma("unroll")                                                           \
        for (int it = 0; it < 4; it++)                                              \
            rw[it] = *(const float4*)(Wb + (size_t)(rbase + it * 32) * K + gk + c4); \
    }

    #define STS_TILE(BUF)                                                           \
    {                                                                               \
        _Pragma("unroll")                                                           \
        for (int it = 0; it < 4; it++) {                                            \
            uint4 t4;                                                               \
            t4.x = f2tf32(ra[it].x); t4.y = f2tf32(ra[it].y);                       \
            t4.z = f2tf32(ra[it].z); t4.w = f2tf32(ra[it].w);                       \
            *(uint4*)(dsm + (BUF) * SA + (rbase + it * 32) * KST + c4) = t4;        \
            uint4 w4;                                                               \
            w4.x = f2tf32(rw[it].x); w4.y = f2tf32(rw[it].y);                       \
            w4.z = f2tf32(rw[it].z); w4.w = f2tf32(rw[it].w);                       \
            *(uint4*)(dsm + (2 + (BUF)) * SA + (rbase + it * 32) * KST + c4) = w4;  \
        }                                                                           \
    }

    LDG_TILE(0);
    STS_TILE(0);
    __syncthreads();

    int buf = 0;
    for (int kt = 0; kt < KT; kt++) {
        if (kt + 1 < KT) LDG_TILE(kt + 1);

        const uint32_t sAaddr = smem0 + (uint32_t)(buf * SA) * 4;
        const uint32_t sWaddr = smem0 + (uint32_t)((2 + buf) * SA) * 4;

        #pragma unroll
        for (int k0 = 0; k0 < BK; k0 += 8) {
            uint32_t afr[2][4], bq[4][4];
            #pragma unroll
            for (int mi = 0; mi < 2; mi++) {
                int row = wm * 32 + mi * 16 + (lg & 1) * 8 + lr;
                int col = k0 + (lg >> 1) * 4;
                ldsm_x4(afr[mi], sAaddr + (uint32_t)(row * KST + col) * 4);
            }
            #pragma unroll
            for (int nip = 0; nip < 4; nip++) {
                int row = wn * 64 + (2 * nip + (lg >> 1)) * 8 + lr;
                int col = k0 + (lg & 1) * 4;
                ldsm_x4(bq[nip], sWaddr + (uint32_t)(row * KST + col) * 4);
            }
            #pragma unroll
            for (int mi = 0; mi < 2; mi++)
                #pragma unroll
                for (int ni = 0; ni < 8; ni++)
                    mma_tf32(acc[mi][ni], afr[mi], &bq[ni >> 1][(ni & 1) * 2]);
        }

        if (kt + 1 < KT) STS_TILE(buf ^ 1);
        __syncthreads();
        buf ^= 1;
    }
    #undef LDG_TILE
    #undef STS_TILE

    const float dtv = (EPI == 2) ? dtp[0] : 0.0f;

    #pragma unroll
    for (int mi = 0; mi < 2; mi++) {
        int row = bm + wm * 32 + mi * 16 + gid;
        #pragma unroll
        for (int ni = 0; ni < 8; ni++) {
            int col = bn + wn * 64 + ni * 8 + 2 * tig;
            float b0 = 0.f, b1 = 0.f;
            if (HAS_BIAS) { b0 = bias[col]; b1 = bias[col + 1]; }
            #pragma unroll
            for (int half = 0; half < 2; half++) {
                int r = row + half * 8;
                float v0 = acc[mi][ni][half * 2 + 0] + b0;
                float v1 = acc[mi][ni][half * 2 + 1] + b1;
                if (ACT == 1) { v0 = v0 / (1.0f + __expf(-v0)); v1 = v1 / (1.0f + __expf(-v1)); }
                else if (ACT == 2) { v0 = tanhf(v0); v1 = tanhf(v1); }
                if (EPI == 1) {
                    const float2 rv = *(const float2*)(res1 + (size_t)r * N + col);
                    v0 += rv.x; v1 += rv.y;
                } else if (EPI == 2) {
                    const float2 rv = *(const float2*)(res1 + (size_t)r * N + col);
                    v0 = dtv * (rv.x + v0); v1 = dtv * (rv.y + v1);
                } else if (EPI == 3) {
                    const float2 ra2 = *(const float2*)(res1 + (size_t)r * N + col);
                    const float2 rb2 = *(const float2*)(res2 + (size_t)r * N + col);
                    v0 += ra2.x + rb2.x; v1 += ra2.y + rb2.y;
                }
                *(float2*)(C + (size_t)r * N + col) = make_float2(v0, v1);
            }
        }
    }
}

// ---------------------------------------------------------------------------
// Sigmoid attention, tensor-core ldmatrix version.
// K/P fragments via ldmatrix; V scalar (conflict-free); all smem pre-converted
// to tf32 bits in the loader; sigmoid via tanh.approx (1 MUFU/element).
// ---------------------------------------------------------------------------
#define AQ  128
#define AKV 32
#define KS2 68      // Ks/Ps row stride (mult of 4 for ldsm alignment)

__global__ __launch_bounds__(256)
void attn_tc_kernel(const float* __restrict__ Qp, const float* __restrict__ Kp,
                    int qstr,
                    const float* __restrict__ V, const float* __restrict__ temp,
                    float* __restrict__ O)
{
    __shared__ uint32_t Ks[AKV][KS2];
    __shared__ uint32_t Vs[AKV][72];
    __shared__ uint32_t Ps[AQ][KS2];

    const uint32_t ksBase = (uint32_t)__cvta_generic_to_shared(&Ks[0][0]);
    const uint32_t psBase = (uint32_t)__cvta_generic_to_shared(&Ps[0][0]);

    const int b = blockIdx.z, h = blockIdx.y;
    const int q0 = blockIdx.x * AQ;
    const int tid = threadIdx.x;
    const int warp = tid >> 5, lane = tid & 31;
    const int gid = lane >> 2, tig = lane & 3;
    const int lg  = lane >> 3, lr  = lane & 7;

    const float hs = 0.0625f * temp[0];   // 0.5 * (HD^-0.5 * temp)
    const size_t baseq  = ((size_t)(b * SEQ + q0)) * qstr + h * HDIM;
    const size_t basek  = ((size_t)(b * SEQ)) * qstr + h * HDIM;
    const size_t basev  = ((size_t)(b * SEQ)) * DIM + h * HDIM;
    const size_t baseo  = ((size_t)(b * SEQ + q0)) * DIM + h * HDIM;

    const int r0 = warp * 16 + gid;

    uint32_t qfr[8][4];
    {
        const float* Qr0 = Qp + baseq + (size_t)r0 * qstr;
        const float* Qr1 = Qr0 + (size_t)8 * qstr;
        #pragma unroll
        for (int kc = 0; kc < 8; kc++) {
            qfr[kc][0] = f2tf32(Qr0[kc * 8 + tig    ]);
            qfr[kc][1] = f2tf32(Qr1[kc * 8 + tig    ]);
            qfr[kc][2] = f2tf32(Qr0[kc * 8 + tig + 4]);
            qfr[kc][3] = f2tf32(Qr1[kc * 8 + tig + 4]);
        }
    }

    float acc_o[8][4];
    #pragma unroll
    for (int nb = 0; nb < 8; nb++)
        #pragma unroll
        for (int r = 0; r < 4; r++) acc_o[nb][r] = 0.0f;
    float rs0 = 0.0f, rs1 = 0.0f;

    for (int m0 = 0; m0 < SEQ; m0 += AKV) {
        __syncthreads();
        #pragma unroll
        for (int it = 0; it < 2; it++) {
            int f = tid + it * 256;
            int r = f >> 4, c4 = (f & 15) * 4;
            float4 kv = *(const float4*)(Kp + basek + (size_t)(m0 + r) * qstr + c4);
            Ks[r][c4] = f2tf32(kv.x); Ks[r][c4 + 1] = f2tf32(kv.y);
            Ks[r][c4 + 2] = f2tf32(kv.z); Ks[r][c4 + 3] = f2tf32(kv.w);
            float4 vv = *(const float4*)(V + basev + (size_t)(m0 + r) * DIM + c4);
            Vs[r][c4] = f2tf32(vv.x); Vs[r][c4 + 1] = f2tf32(vv.y);
            Vs[r][c4 + 2] = f2tf32(vv.z); Vs[r][c4 + 3] = f2tf32(vv.w);
        }
        __syncthreads();

        // S = Q @ K^T  (warp: 16 x 32), K fragments via ldmatrix
        float acc_s[4][4] = {};
        #pragma unroll
        for (int k0 = 0; k0 < 64; k0 += 8) {
            uint32_t bK[2][4];
            #pragma unroll
            for (int nip = 0; nip < 2; nip++) {
                int row = (2 * nip + (lg >> 1)) * 8 + lr;
                int col = k0 + (lg & 1) * 4;
                ldsm_x4(bK[nip], ksBase + (uint32_t)(row * KS2 + col) * 4);
            }
            #pragma unroll
            for (int ni = 0; ni < 4; ni++)
                mma_tf32(acc_s[ni], qfr[k0 >> 3], &bK[ni >> 1][(ni & 1) * 2]);
        }

        // sigmoid = 0.5*tanh(s*scale/2) + 0.5 ; park tf32 bits in Ps
        #pragma unroll
        for (int nb = 0; nb < 4; nb++) {
            float s00 = fmaf(0.5f, tanh_fast(acc_s[nb][0] * hs), 0.5f);
            float s01 = fmaf(0.5f, tanh_fast(acc_s[nb][1] * hs), 0.5f);
            float s10 = fmaf(0.5f, tanh_fast(acc_s[nb][2] * hs), 0.5f);
            float s11 = fmaf(0.5f, tanh_fast(acc_s[nb][3] * hs), 0.5f);
            rs0 += s00 + s01;
            rs1 += s10 + s11;
            uint2 p0 = make_uint2(f2tf32(s00), f2tf32(s01));
            uint2 p1 = make_uint2(f2tf32(s10), f2tf32(s11));
            *(uint2*)&Ps[r0    ][nb * 8 + 2 * tig] = p0;
            *(uint2*)&Ps[r0 + 8][nb * 8 + 2 * tig] = p1;
        }
        __syncwarp();    // Ps rows are warp-private

        // O += P @ V : P fragments via ldmatrix, V scalar (pre-converted)
        #pragma unroll
        for (int k0 = 0; k0 < 32; k0 += 8) {
            uint32_t aP[4];
            {
                int row = warp * 16 + (lg & 1) * 8 + lr;
                int col = k0 + (lg >> 1) * 4;
                ldsm_x4(aP, psBase + (uint32_t)(row * KS2 + col) * 4);
            }
            #pragma unroll
            for (int nb = 0; nb < 8; nb++) {
                uint32_t bfr[2];
                bfr[0] = Vs[k0 + tig    ][nb * 8 + gid];
                bfr[1] = Vs[k0 + tig + 4][nb * 8 + gid];
                mma_tf32(acc_o[nb], aP, bfr);
            }
        }
        __syncwarp();    // Ps rewritten next iteration (warp-local)
    }

    rs0 += __shfl_xor_sync(0xffffffffu, rs0, 1);
    rs0 += __shfl_xor_sync(0xffffffffu, rs0, 2);
    rs1 += __shfl_xor_sync(0xffffffffu, rs1, 1);
    rs1 += __shfl_xor_sync(0xffffffffu, rs1, 2);
    const float inv0 = 1.0f / fmaxf(rs0, 1.0f);
    const float inv1 = 1.0f / fmaxf(rs1, 1.0f);

    float* O0 = O + baseo + (size_t)r0 * DIM;
    float* O1 = O0 + 8 * DIM;
    #pragma unroll
    for (int nb = 0; nb < 8; nb++) {
        int col = nb * 8 + 2 * tig;
        *(float2*)(O0 + col) = make_float2(acc_o[nb][0] * inv0, acc_o[nb][1] * inv0);
        *(float2*)(O1 + col) = make_float2(acc_o[nb][2] * inv1, acc_o[nb][3] * inv1);
    }
}

// ---------------------------------------------------------------------------
// Host-side dispatch
// ---------------------------------------------------------------------------
struct Seg { const float* p; int s; };

template<int ACT, int EPI, bool HAS_BIAS>
static void launch_gemm2(cudaStream_t st, const Seg* seg, int nseg,
                         const float* W0, const float* W1, int wsplit,
                         const float* bias,
                         const float* res1, const float* res2, const float* dtp,
                         float* C, int M, int N, int K)
{
    cudaFuncSetAttribute(gemm_tc_kernel<ACT, EPI, HAS_BIAS>,
                         cudaFuncAttributeMaxDynamicSharedMemorySize, GEMM_SMEM);
    const float* p0 = seg[0].p;                     int s0 = seg[0].s;
    const float* p1 = (nseg > 1) ? seg[1].p : p0;   int s1 = (nseg > 1) ? seg[1].s : s0;
    const float* p2 = (nseg > 2) ? seg[2].p : p0;   int s2 = (nseg > 2) ? seg[2].s : s0;
    const float* p3 = (nseg > 3) ? seg[3].p : p0;   int s3 = (nseg > 3) ? seg[3].s : s0;
    dim3 g(N / BN, M / BM), b(256);
    gemm_tc_kernel<ACT, EPI, HAS_BIAS><<<g, b, GEMM_SMEM, st>>>(
        p0, p1, p2, p3, s0, s1, s2, s3, W0, W1, wsplit,
        bias, res1, res2, dtp, C, M, N, K);
}

template<int ACT, int EPI, bool HAS_BIAS>
static void launch_gemm(cudaStream_t st, const Seg* seg, int nseg,
                        const float* W, const float* bias,
                        const float* res1, const float* res2, const float* dtp,
                        float* C, int M, int N, int K)
{
    launch_gemm2<ACT, EPI, HAS_BIAS>(st, seg, nseg, W, W, 1 << 30,
                                     bias, res1, res2, dtp, C, M, N, K);
}

static float* sym(const void* s)
{
    void* p = nullptr;
    cudaGetSymbolAddress(&p, s);
    return (float*)p;
}

extern "C" void kernel_launch(void* const* d_in, const int* in_sizes, int n_in,
                              void* d_out, int out_size)
{
    const float* z     = (const float*)d_in[0];
    const float* conn  = (const float*)d_in[1];
    const float* w_z   = (const float*)d_in[2];
    const float* w_c   = (const float*)d_in[3];
    const float* w_mlp = (const float*)d_in[4];
    const float* f_w1  = (const float*)d_in[5];
    const float* f_b1  = (const float*)d_in[6];
    const float* f_w2  = (const float*)d_in[7];
    const float* f_b2  = (const float*)d_in[8];
    const float* g_w1  = (const float*)d_in[9];
    const float* g_b1  = (const float*)d_in[10];
    const float* g_w2  = (const float*)d_in[11];
    const float* g_b2  = (const float*)d_in[12];
    const float* dt    = (const float*)d_in[13];
    const float* q_w   = (const float*)d_in[14];
    const float* k_w   = (const float*)d_in[15];
    const float* v_w   = (const float*)d_in[16];
    const float* o_w   = (const float*)d_in[17];
    const float* temp  = (const float*)d_in[18];
    const float* cu_w1 = (const float*)d_in[19];
    const float* cu_b1 = (const float*)d_in[20];
    const float* cu_w2 = (const float*)d_in[21];
    const float* cu_b2 = (const float*)d_in[22];
    const float* m_w1  = (const float*)d_in[23];
    const float* m_b1  = (const float*)d_in[24];
    const float* m_w2  = (const float*)d_in[25];
    const float* m_b2  = (const float*)d_in[26];

    float* out_z2 = (float*)d_out;
    float* out_cn = out_z2 + (size_t)NTOK * DIM;
    float* out_zb = out_cn + (size_t)NTOK * DIM;

    float* zn   = sym(g_zn);
    float* cn   = sym(g_cn);
    float* hf   = sym(g_hf);
    float* dzl  = sym(g_dzl);
    float* gh   = sym(g_gh);
    float* dz   = sym(g_dz);
    float* QKb  = sym(g_QK);
    float* Vb   = sym(g_V);
    float* attn = sym(g_attn);
    float* z1   = sym(g_z1);
    float* hcu  = sym(g_hcu);
    float* z1n  = sym(g_z1n);
    float* h4   = sym(g_h4);

    const int ND = NTOK * DIM;

    // Side stream + events (created once; every call performs identical work)
    static cudaStream_t s2 = nullptr;
    static cudaEvent_t evF1 = nullptr, evJ1 = nullptr, evF2 = nullptr, evJ2 = nullptr;
    if (!s2) {
        cudaStreamCreateWithFlags(&s2, cudaStreamNonBlocking);
        cudaEventCreateWithFlags(&evF1, cudaEventDisableTiming);
        cudaEventCreateWithFlags(&evJ1, cudaEventDisableTiming);
        cudaEventCreateWithFlags(&evF2, cudaEventDisableTiming);
        cudaEventCreateWithFlags(&evJ2, cudaEventDisableTiming);
    }
    cudaStream_t s0 = 0;   // default (captured) stream

    // 1. norms (fused pair) on main stream
    rms2_kernel<<<2 * NTOK, 256, 0, s0>>>(z, w_z, zn, conn, w_c, cn);

    // ---- fork 1: chain B (QK, V, attention) on s2; chain A (f/g) on s0 ----
    cudaEventRecord(evF1, s0);
    cudaStreamWaitEvent(s2, evF1, 0);

    // chain B (s2): z_before copy + projections + attention
    cudaMemcpyAsync(out_zb, z, (size_t)ND * sizeof(float),
                    cudaMemcpyDeviceToDevice, s2);
    { Seg s[2] = {{zn, DIM}, {cn, DIM}};
      launch_gemm2<0,0,false>(s2, s, 2, q_w, k_w, DIM, nullptr,
                              nullptr, nullptr, nullptr,
                              QKb, NTOK, 2*DIM, 2*DIM); }
    { Seg s[1] = {{zn, DIM}};
      launch_gemm<0,0,false>(s2, s, 1, v_w, nullptr, nullptr, nullptr, nullptr,
                             Vb, NTOK, DIM, DIM); }
    {
        dim3 g(SEQ / AQ, NHEAD, BATCH), b(256);
        attn_tc_kernel<<<g, b, 0, s2>>>(QKb, QKb + DIM, 2 * DIM, Vb, temp, attn);
    }
    cudaEventRecord(evJ1, s2);

    // chain A (s0): vector field + gamma
    { Seg s[1] = {{zn, DIM}};
      launch_gemm<1,0,true>(s0, s, 1, f_w1, f_b1, nullptr, nullptr, nullptr,
                            hf, NTOK, 2*DIM, DIM); }
    { Seg s[2] = {{hf, 2*DIM}, {hf + DIM, 2*DIM}};
      launch_gemm<0,0,true>(s0, s, 2, f_w2, f_b2, nullptr, nullptr, nullptr,
                            dzl, NTOK, DIM, 2*DIM); }
    { Seg s[2] = {{cn, DIM}, {dzl, DIM}};
      launch_gemm<2,0,true>(s0, s, 2, g_w1, g_b1, nullptr, nullptr, nullptr,
                            gh, NTOK, DIM, 2*DIM); }
    { Seg s[1] = {{gh, DIM}};
      launch_gemm<0,2,true>(s0, s, 1, g_w2, g_b2, dzl, nullptr, dt,
                            dz, NTOK, DIM, DIM); }

    // ---- join 1: o_w needs attn (B) and dz (A) ----
    cudaStreamWaitEvent(s0, evJ1, 0);

    // 6. z1 = z + dz + attn @ o_w^T
    { Seg s[1] = {{attn, DIM}};
      launch_gemm<0,3,false>(s0, s, 1, o_w, nullptr, z, dz, nullptr,
                             z1, NTOK, DIM, DIM); }

    // ---- fork 2: chain C (connection update) on s2; chain D (MLP) on s0 ----
    cudaEventRecord(evF2, s0);
    cudaStreamWaitEvent(s2, evF2, 0);

    // chain C (s2): conn_new
    { Seg s[3] = {{conn, DIM}, {z1, DIM}, {dz, DIM}};
      launch_gemm<1,0,true>(s2, s, 3, cu_w1, cu_b1, nullptr, nullptr, nullptr,
                            hcu, NTOK, 2*DIM, 3*DIM); }
    { Seg s[2] = {{hcu, 2*DIM}, {hcu + DIM, 2*DIM}};
      launch_gemm<0,1,true>(s2, s, 2, cu_w2, cu_b2, conn, nullptr, nullptr,
                            out_cn, NTOK, DIM, 2*DIM); }
    cudaEventRecord(evJ2, s2);

    // chain D (s0): MLP block
    rms_kernel<<<NTOK, 256, 0, s0>>>(z1, w_mlp, z1n);
    { Seg s[1] = {{z1n, DIM}};
      launch_gemm<1,0,true>(s0, s, 1, m_w1, m_b1, nullptr, nullptr, nullptr,
                            h4, NTOK, 4*DIM, DIM); }
    { Seg s[4] = {{h4, 4*DIM}, {h4 + DIM, 4*DIM}, {h4 + 2*DIM, 4*DIM}, {h4 + 3*DIM, 4*DIM}};
      launch_gemm<0,1,true>(s0, s, 4, m_w2, m_b2, z1, nullptr, nullptr,
                            out_z2, NTOK, DIM, 4*DIM); }

    // ---- join 2: everything back on the captured stream ----
    cudaStreamWaitEvent(s0, evJ2, 0);
}